// round 1
// baseline (speedup 1.0000x reference)
#include <cuda_runtime.h>
#include <cuda_bf16.h>
#include <math.h>

#define B_SZ 256
#define DIM 2048
#define NH 8
#define HD 256
#define EPS 1e-5f

// ---------------- scratch (device globals; no allocation allowed) ----------
__device__ float g_pooled[B_SZ * DIM];       // mean-pooled mem
__device__ float g_qv[B_SZ * 2 * DIM];       // qv = f_ad @ qv_W^T
__device__ float g_k1[B_SZ * DIM];           // k1 = pooled @ k1_W^T
__device__ float g_qn[B_SZ * DIM];           // q_norm
__device__ float g_k1n[B_SZ * DIM];          // k1_norm
__device__ float g_k2n[B_SZ * DIM];          // k2_norm

// ---------------- helpers ----------------
__device__ __forceinline__ float warp_sum(float v) {
    v += __shfl_xor_sync(0xffffffffu, v, 16);
    v += __shfl_xor_sync(0xffffffffu, v, 8);
    v += __shfl_xor_sync(0xffffffffu, v, 4);
    v += __shfl_xor_sync(0xffffffffu, v, 2);
    v += __shfl_xor_sync(0xffffffffu, v, 1);
    return v;
}

__device__ __forceinline__ float gelu_tanh(float x) {
    const float k = 0.7978845608028654f;   // sqrt(2/pi)
    float x3 = x * x * x;
    return 0.5f * x * (1.0f + tanhf(k * (x + 0.044715f * x3)));
}

// ---------------- 1) mean-pool mem over 64 spatial elems -------------------
// one warp per (b, d) output; lane reads 2 contiguous floats -> fully coalesced
__global__ void pool_kernel(const float* __restrict__ mem, float* __restrict__ pooled) {
    int gw   = (blockIdx.x * blockDim.x + threadIdx.x) >> 5;   // 0 .. 524287
    int lane = threadIdx.x & 31;
    if (gw >= B_SZ * DIM) return;
    const float2 v = *(const float2*)&mem[(size_t)gw * 64 + lane * 2];
    float s = warp_sum(v.x + v.y);
    if (lane == 0) pooled[gw] = s * (1.0f / 64.0f);
}

// ---------------- 2) AGF branch + per-head LN -> k2_norm -------------------
// one block per batch row
__global__ void agf_kernel(const float* __restrict__ f_age, const float* __restrict__ age_gap,
                           const float* __restrict__ rW, const float* __restrict__ rb,
                           const float* __restrict__ eW, const float* __restrict__ eb,
                           const float* __restrict__ lw, const float* __restrict__ lb,
                           float* __restrict__ k2n) {
    __shared__ float srow[DIM];
    __shared__ float pr[8];
    int b = blockIdx.x, t = threadIdx.x;
    int wid = t >> 5, lane = t & 31;

    // red = dot(f_age[b], rW) + rb
    float part = 0.f;
    for (int i = t; i < DIM; i += 256) part += f_age[(size_t)b * DIM + i] * rW[i];
    part = warp_sum(part);
    if (lane == 0) pr[wid] = part;
    __syncthreads();
    float red = rb[0];
    #pragma unroll
    for (int i = 0; i < 8; i++) red += pr[i];
    float ag = age_gap[b];

    // k2 row
    for (int i = t; i < DIM; i += 256) {
        srow[i] = f_age[(size_t)b * DIM + i] + eW[i * 2 + 0] * red + eW[i * 2 + 1] * ag + eb[i];
    }
    __syncthreads();

    // per-head LN (warp wid owns head wid, 8 elems/lane)
    float x[8], s = 0.f, ss = 0.f;
    #pragma unroll
    for (int j = 0; j < 8; j++) {
        x[j] = srow[wid * HD + lane + 32 * j];
        s += x[j]; ss += x[j] * x[j];
    }
    s = warp_sum(s); ss = warp_sum(ss);
    float mu = s * (1.0f / HD);
    float inv = rsqrtf(ss * (1.0f / HD) - mu * mu + EPS);
    #pragma unroll
    for (int j = 0; j < 8; j++) {
        int i = lane + 32 * j;
        k2n[(size_t)b * DIM + wid * HD + i] = (x[j] - mu) * inv * lw[i] + lb[i];
    }
}

// ---------------- 3) GEMM: C[M,N] = A[M,K] * W[N,K]^T (both K-major) -------
// 64x64x16 tiles, 256 threads, 4x4 register blocking
#define BM 64
#define BN 64
#define BK 16
__global__ void gemm_nt(const float* __restrict__ A, const float* __restrict__ W,
                        float* __restrict__ C, int M, int N, int K) {
    __shared__ float As[BK][BM];
    __shared__ float Ws[BK][BN];
    int tid = threadIdx.x;
    int bm = blockIdx.y * BM, bn = blockIdx.x * BN;
    int lr = tid >> 2;             // 0..63 tile row for loads
    int lc = (tid & 3) * 4;        // 0,4,8,12 k-offset for loads
    int tr = (tid >> 4) * 4;       // compute row base
    int tc = (tid & 15) * 4;       // compute col base
    float acc[4][4] = {};

    for (int k0 = 0; k0 < K; k0 += BK) {
        float4 av = *(const float4*)&A[(size_t)(bm + lr) * K + k0 + lc];
        float4 wv = *(const float4*)&W[(size_t)(bn + lr) * K + k0 + lc];
        __syncthreads();
        As[lc + 0][lr] = av.x; As[lc + 1][lr] = av.y; As[lc + 2][lr] = av.z; As[lc + 3][lr] = av.w;
        Ws[lc + 0][lr] = wv.x; Ws[lc + 1][lr] = wv.y; Ws[lc + 2][lr] = wv.z; Ws[lc + 3][lr] = wv.w;
        __syncthreads();
        #pragma unroll
        for (int kk = 0; kk < BK; kk++) {
            float4 a = *(const float4*)&As[kk][tr];
            float4 w = *(const float4*)&Ws[kk][tc];
            float ar[4] = {a.x, a.y, a.z, a.w};
            float wr[4] = {w.x, w.y, w.z, w.w};
            #pragma unroll
            for (int i = 0; i < 4; i++)
                #pragma unroll
                for (int j = 0; j < 4; j++)
                    acc[i][j] = fmaf(ar[i], wr[j], acc[i][j]);
        }
    }
    #pragma unroll
    for (int i = 0; i < 4; i++)
        #pragma unroll
        for (int j = 0; j < 4; j++)
            C[(size_t)(bm + tr + i) * N + bn + tc + j] = acc[i][j];
}

// ---------------- 4) per-head LN of q (from qv) and k1 ---------------------
// one warp per (b,h) row; rows [0,2048) = q, [2048,4096) = k1
__global__ void ln_heads(const float* __restrict__ qv, const float* __restrict__ k1,
                         const float* __restrict__ lw, const float* __restrict__ lb,
                         float* __restrict__ qn, float* __restrict__ k1n) {
    int gw   = (blockIdx.x * blockDim.x + threadIdx.x) >> 5;
    int lane = threadIdx.x & 31;
    if (gw >= 2 * B_SZ * NH) return;
    int r = gw & (B_SZ * NH - 1);
    int b = r >> 3, h = r & 7;
    const float* src;
    float* dst;
    if (gw < B_SZ * NH) { src = qv + (size_t)b * 2 * DIM + h * HD; dst = qn  + (size_t)b * DIM + h * HD; }
    else                { src = k1 + (size_t)b * DIM     + h * HD; dst = k1n + (size_t)b * DIM + h * HD; }

    float x[8], s = 0.f, ss = 0.f;
    #pragma unroll
    for (int j = 0; j < 8; j++) {
        x[j] = src[lane + 32 * j];
        s += x[j]; ss += x[j] * x[j];
    }
    s = warp_sum(s); ss = warp_sum(ss);
    float mu = s * (1.0f / HD);
    float inv = rsqrtf(ss * (1.0f / HD) - mu * mu + EPS);
    #pragma unroll
    for (int j = 0; j < 8; j++) {
        int i = lane + 32 * j;
        dst[i] = (x[j] - mu) * inv * lw[i] + lb[i];
    }
}

// ---------------- 5) fused: 2x attention + 2x conv1d + LNs + GELUs ---------
// one block (256 thr = 8 warps) per batch; warp w = head/channel w
__global__ void __launch_bounds__(256, 4)
fused_attn(const float* __restrict__ qn, const float* __restrict__ k1n,
           const float* __restrict__ k2n, const float* __restrict__ qv,
           const float* __restrict__ lw, const float* __restrict__ lb,
           const float* __restrict__ l2w, const float* __restrict__ l2b,
           const float* __restrict__ w1, const float* __restrict__ w2,
           float* __restrict__ out) {
    __shared__ float sQ[DIM], sK1[DIM], sK2[DIM], sV[DIM], sO1[DIM];
    __shared__ float cw1[192], cw2[192];
    __shared__ float rs[8], rss[8];
    float* sO2 = sK1;   // alias: k1_norm dead after attn1 scores

    int b = blockIdx.x, t = threadIdx.x;
    int wid = t >> 5, lane = t & 31;

    for (int i = t; i < DIM; i += 256) {
        sQ[i]  = qn[(size_t)b * DIM + i];
        sK1[i] = k1n[(size_t)b * DIM + i];
        sK2[i] = k2n[(size_t)b * DIM + i];
        sV[i]  = qv[(size_t)b * 2 * DIM + DIM + i];
    }
    if (t < 192) { cw1[t] = w1[t]; cw2[t] = w2[t]; }
    __syncthreads();

    // ---- attention 1 (q_norm vs k1_norm, value v) -> sO1 ----
    {
        float a[8];
        #pragma unroll
        for (int s = 0; s < 8; s++) {
            float p = 0.f;
            #pragma unroll
            for (int j = 0; j < 8; j++)
                p = fmaf(sQ[wid * HD + lane + 32 * j], sK1[s * HD + lane + 32 * j], p);
            a[s] = warp_sum(p) * (1.0f / 16.0f);   // 1/sqrt(256)
        }
        float m = a[0];
        #pragma unroll
        for (int s = 1; s < 8; s++) m = fmaxf(m, a[s]);
        float sum = 0.f;
        #pragma unroll
        for (int s = 0; s < 8; s++) { a[s] = expf(a[s] - m); sum += a[s]; }
        float inv = 1.0f / sum;
        #pragma unroll
        for (int j = 0; j < 8; j++) {
            int c = lane + 32 * j;
            float acc = 0.f;
            #pragma unroll
            for (int s = 0; s < 8; s++) acc = fmaf(a[s], sV[s * HD + c], acc);
            sO1[wid * HD + c] = acc * inv;
        }
    }
    __syncthreads();

    // ---- attention 2 (q_norm vs k2_norm) -> sO2 (aliases sK1) ----
    {
        float a[8];
        #pragma unroll
        for (int s = 0; s < 8; s++) {
            float p = 0.f;
            #pragma unroll
            for (int j = 0; j < 8; j++)
                p = fmaf(sQ[wid * HD + lane + 32 * j], sK2[s * HD + lane + 32 * j], p);
            a[s] = warp_sum(p) * (1.0f / 16.0f);
        }
        float m = a[0];
        #pragma unroll
        for (int s = 1; s < 8; s++) m = fmaxf(m, a[s]);
        float sum = 0.f;
        #pragma unroll
        for (int s = 0; s < 8; s++) { a[s] = expf(a[s] - m); sum += a[s]; }
        float inv = 1.0f / sum;
        #pragma unroll
        for (int j = 0; j < 8; j++) {
            int c = lane + 32 * j;
            float acc = 0.f;
            #pragma unroll
            for (int s = 0; s < 8; s++) acc = fmaf(a[s], sV[s * HD + c], acc);
            sO2[wid * HD + c] = acc * inv;
        }
    }
    __syncthreads();

    // ---- conv1d (C=8, K=3, pad 1) on both, per-head LN each, sum + v, LN, gelu ----
    float c1[8], c2[8], g[8];
    #pragma unroll
    for (int j = 0; j < 8; j++) {
        int l = lane + 32 * j;
        float a1 = 0.f, a2 = 0.f;
        #pragma unroll
        for (int i = 0; i < 8; i++) {
            float xm = (l > 0)   ? sO1[i * HD + l - 1] : 0.f;
            float x0 =             sO1[i * HD + l];
            float xp = (l < 255) ? sO1[i * HD + l + 1] : 0.f;
            a1 = fmaf(cw1[wid * 24 + i * 3 + 0], xm, a1);
            a1 = fmaf(cw1[wid * 24 + i * 3 + 1], x0, a1);
            a1 = fmaf(cw1[wid * 24 + i * 3 + 2], xp, a1);
            float ym = (l > 0)   ? sO2[i * HD + l - 1] : 0.f;
            float y0 =             sO2[i * HD + l];
            float yp = (l < 255) ? sO2[i * HD + l + 1] : 0.f;
            a2 = fmaf(cw2[wid * 24 + i * 3 + 0], ym, a2);
            a2 = fmaf(cw2[wid * 24 + i * 3 + 1], y0, a2);
            a2 = fmaf(cw2[wid * 24 + i * 3 + 2], yp, a2);
        }
        c1[j] = a1; c2[j] = a2;
    }

    // per-head LN of conv outputs (warp-local)
    {
        float s = 0.f, ss = 0.f;
        #pragma unroll
        for (int j = 0; j < 8; j++) { s += c1[j]; ss += c1[j] * c1[j]; }
        s = warp_sum(s); ss = warp_sum(ss);
        float mu = s * (1.0f / HD), inv = rsqrtf(ss * (1.0f / HD) - mu * mu + EPS);
        #pragma unroll
        for (int j = 0; j < 8; j++) { int i = lane + 32 * j; c1[j] = (c1[j] - mu) * inv * lw[i] + lb[i]; }
    }
    {
        float s = 0.f, ss = 0.f;
        #pragma unroll
        for (int j = 0; j < 8; j++) { s += c2[j]; ss += c2[j] * c2[j]; }
        s = warp_sum(s); ss = warp_sum(ss);
        float mu = s * (1.0f / HD), inv = rsqrtf(ss * (1.0f / HD) - mu * mu + EPS);
        #pragma unroll
        for (int j = 0; j < 8; j++) { int i = lane + 32 * j; c2[j] = (c2[j] - mu) * inv * lw[i] + lb[i]; }
    }
    // sum + v, per-head LN, gelu
    {
        float x[8], s = 0.f, ss = 0.f;
        #pragma unroll
        for (int j = 0; j < 8; j++) {
            x[j] = c1[j] + c2[j] + sV[wid * HD + lane + 32 * j];
            s += x[j]; ss += x[j] * x[j];
        }
        s = warp_sum(s); ss = warp_sum(ss);
        float mu = s * (1.0f / HD), inv = rsqrtf(ss * (1.0f / HD) - mu * mu + EPS);
        #pragma unroll
        for (int j = 0; j < 8; j++) {
            int i = lane + 32 * j;
            g[j] = gelu_tanh((x[j] - mu) * inv * lw[i] + lb[i]);
        }
    }

    // final LN2 over full 2048 + gelu
    {
        float s = 0.f, ss = 0.f;
        #pragma unroll
        for (int j = 0; j < 8; j++) { s += g[j]; ss += g[j] * g[j]; }
        s = warp_sum(s); ss = warp_sum(ss);
        if (lane == 0) { rs[wid] = s; rss[wid] = ss; }
        __syncthreads();
        float ts = 0.f, tss = 0.f;
        #pragma unroll
        for (int i = 0; i < 8; i++) { ts += rs[i]; tss += rss[i]; }
        float mu = ts * (1.0f / DIM), inv = rsqrtf(tss * (1.0f / DIM) - mu * mu + EPS);
        #pragma unroll
        for (int j = 0; j < 8; j++) {
            int idx = wid * HD + lane + 32 * j;
            float y = (g[j] - mu) * inv * l2w[idx] + l2b[idx];
            out[(size_t)b * DIM + idx] = gelu_tanh(y);
        }
    }
}

// ---------------- launch ----------------
extern "C" void kernel_launch(void* const* d_in, const int* in_sizes, int n_in,
                              void* d_out, int out_size) {
    const float* f_ad    = (const float*)d_in[0];
    const float* f_age   = (const float*)d_in[1];
    const float* mem     = (const float*)d_in[2];
    const float* age_gap = (const float*)d_in[3];
    const float* qv_W    = (const float*)d_in[4];
    const float* k1_W    = (const float*)d_in[5];
    // d_in[6] = k2_W : dead in the reference (never applied) — skipped
    const float* ln_w    = (const float*)d_in[7];
    const float* ln_b    = (const float*)d_in[8];
    const float* ln2_w   = (const float*)d_in[9];
    const float* ln2_b   = (const float*)d_in[10];
    const float* agf_rW  = (const float*)d_in[11];
    const float* agf_rb  = (const float*)d_in[12];
    const float* agf_eW  = (const float*)d_in[13];
    const float* agf_eb  = (const float*)d_in[14];
    const float* c1W     = (const float*)d_in[15];
    const float* c2W     = (const float*)d_in[16];
    float* out = (float*)d_out;

    float *pooled, *qvb, *k1b, *qn, *k1n, *k2n;
    cudaGetSymbolAddress((void**)&pooled, g_pooled);
    cudaGetSymbolAddress((void**)&qvb, g_qv);
    cudaGetSymbolAddress((void**)&k1b, g_k1);
    cudaGetSymbolAddress((void**)&qn, g_qn);
    cudaGetSymbolAddress((void**)&k1n, g_k1n);
    cudaGetSymbolAddress((void**)&k2n, g_k2n);

    // 1) pool mem (dominant HBM stream: 128 MB)
    pool_kernel<<<(B_SZ * DIM * 32) / 256, 256>>>(mem, pooled);
    // 2) AGF + LN -> k2_norm (independent of pool/gemm)
    agf_kernel<<<B_SZ, 256>>>(f_age, age_gap, agf_rW, agf_rb, agf_eW, agf_eb, ln_w, ln_b, k2n);
    // 3) GEMMs
    gemm_nt<<<dim3(2 * DIM / BN, B_SZ / BM), 256>>>(f_ad, qv_W, qvb, B_SZ, 2 * DIM, DIM);
    gemm_nt<<<dim3(DIM / BN, B_SZ / BM), 256>>>(pooled, k1_W, k1b, B_SZ, DIM, DIM);
    // 4) per-head LN of q and k1
    ln_heads<<<(2 * B_SZ * NH) / 8, 256>>>(qvb, k1b, ln_w, ln_b, qn, k1n);
    // 5) fused attention + conv + epilogue
    fused_attn<<<B_SZ, 256>>>(qn, k1n, k2n, qvb, ln_w, ln_b, ln2_w, ln2_b, c1W, c2W, out);
}

// round 3
// speedup vs baseline: 1.5826x; 1.5826x over previous
#include <cuda_runtime.h>
#include <cuda_bf16.h>
#include <math.h>
#include <stdint.h>

#define B_SZ 256
#define DIM 2048
#define NH 8
#define HD 256
#define EPS 1e-5f

// ---------------- scratch (device globals; no allocation allowed) ----------
__device__ float g_pooled[B_SZ * DIM];
__device__ float g_qv[B_SZ * 2 * DIM];
__device__ float g_k1[B_SZ * DIM];
__device__ float g_qn[B_SZ * DIM];
__device__ float g_k1n[B_SZ * DIM];
__device__ float g_k2n[B_SZ * DIM];

// ---------------- helpers ----------------
__device__ __forceinline__ float warp_sum(float v) {
    v += __shfl_xor_sync(0xffffffffu, v, 16);
    v += __shfl_xor_sync(0xffffffffu, v, 8);
    v += __shfl_xor_sync(0xffffffffu, v, 4);
    v += __shfl_xor_sync(0xffffffffu, v, 2);
    v += __shfl_xor_sync(0xffffffffu, v, 1);
    return v;
}

__device__ __forceinline__ float gelu_tanh(float x) {
    const float k = 0.7978845608028654f;
    float x3 = x * x * x;
    return 0.5f * x * (1.0f + tanhf(k * (x + 0.044715f * x3)));
}

// bf16 mma: D(16x8,f32) += A(16x16,bf16) * B(16x8,bf16)
__device__ __forceinline__ void mma16816(float* d, const uint32_t* a, const uint32_t* b) {
    asm volatile(
        "mma.sync.aligned.m16n8k16.row.col.f32.bf16.bf16.f32 "
        "{%0,%1,%2,%3}, {%4,%5,%6,%7}, {%8,%9}, {%0,%1,%2,%3};"
        : "+f"(d[0]), "+f"(d[1]), "+f"(d[2]), "+f"(d[3])
        : "r"(a[0]), "r"(a[1]), "r"(a[2]), "r"(a[3]), "r"(b[0]), "r"(b[1]));
}

// ---------------- 1) mean-pool mem over 64 spatial elems -------------------
__global__ void pool_kernel(const float* __restrict__ mem, float* __restrict__ pooled) {
    int gw   = (blockIdx.x * blockDim.x + threadIdx.x) >> 5;
    int lane = threadIdx.x & 31;
    if (gw >= B_SZ * DIM) return;
    const float2 v = *(const float2*)&mem[(size_t)gw * 64 + lane * 2];
    float s = warp_sum(v.x + v.y);
    if (lane == 0) pooled[gw] = s * (1.0f / 64.0f);
}

// ---------------- 2) AGF branch + per-head LN -> k2_norm -------------------
__global__ void agf_kernel(const float* __restrict__ f_age, const float* __restrict__ age_gap,
                           const float* __restrict__ rW, const float* __restrict__ rb,
                           const float* __restrict__ eW, const float* __restrict__ eb,
                           const float* __restrict__ lw, const float* __restrict__ lb,
                           float* __restrict__ k2n) {
    __shared__ float srow[DIM];
    __shared__ float pr[8];
    int b = blockIdx.x, t = threadIdx.x;
    int wid = t >> 5, lane = t & 31;

    float part = 0.f;
    for (int i = t; i < DIM; i += 256) part += f_age[(size_t)b * DIM + i] * rW[i];
    part = warp_sum(part);
    if (lane == 0) pr[wid] = part;
    __syncthreads();
    float red = rb[0];
    #pragma unroll
    for (int i = 0; i < 8; i++) red += pr[i];
    float ag = age_gap[b];

    for (int i = t; i < DIM; i += 256) {
        srow[i] = f_age[(size_t)b * DIM + i] + eW[i * 2 + 0] * red + eW[i * 2 + 1] * ag + eb[i];
    }
    __syncthreads();

    float x[8], s = 0.f, ss = 0.f;
    #pragma unroll
    for (int j = 0; j < 8; j++) {
        x[j] = srow[wid * HD + lane + 32 * j];
        s += x[j]; ss += x[j] * x[j];
    }
    s = warp_sum(s); ss = warp_sum(ss);
    float mu = s * (1.0f / HD);
    float inv = rsqrtf(ss * (1.0f / HD) - mu * mu + EPS);
    #pragma unroll
    for (int j = 0; j < 8; j++) {
        int i = lane + 32 * j;
        k2n[(size_t)b * DIM + wid * HD + i] = (x[j] - mu) * inv * lw[i] + lb[i];
    }
}

// ---------------- 3) tensor-core GEMM via mma.sync (split-bf16 3-term) -----
// C[m,n] = sum_k A[m,k] * W[n,k];  D += Ah*Bh + Ah*Bl + Al*Bh (fp32 accum)
// CTA tile M=128 N=128, K-chunks of 64. 8 warps in 2x4; warp tile 64x32.
// grid.x = ntile (0..47: 0-31 -> qv_W, 32-47 -> k1_W), grid.y = mtile (0..1)
#define PITCH 144                      // 72 bf16 per row (64 data + 8 pad) -> conflict-free
#define TILE_BYTES (128 * PITCH)       // 18432
#define OFF_AH 0
#define OFF_AL TILE_BYTES
#define OFF_BH (2 * TILE_BYTES)
#define OFF_BL (3 * TILE_BYTES)
#define GEMM_SMEM (4 * TILE_BYTES)     // 73728

__global__ void __launch_bounds__(256, 1)
gemm_tc(const float* __restrict__ f_ad, const float* __restrict__ pooled,
        const float* __restrict__ Wqv, const float* __restrict__ Wk1,
        float* __restrict__ Cqv, float* __restrict__ Ck1) {
    extern __shared__ char sm[];
    int tid = threadIdx.x, wid = tid >> 5, lane = tid & 31;
    int ntile = blockIdx.x, mtile = blockIdx.y;

    bool is_qv = ntile < 32;
    const float* A = is_qv ? f_ad : pooled;
    const float* W = is_qv ? (Wqv + (size_t)ntile * 128 * DIM)
                           : (Wk1 + (size_t)(ntile - 32) * 128 * DIM);
    float* C;
    int ldc, ncol0;
    if (is_qv) { C = Cqv; ldc = 2 * DIM; ncol0 = ntile * 128; }
    else       { C = Ck1; ldc = DIM;     ncol0 = (ntile - 32) * 128; }

    // loader: one row per thread (0..127 = A rows, 128..255 = W rows)
    const float* src = (tid < 128)
        ? (A + (size_t)(mtile * 128 + tid) * DIM)
        : (W + (size_t)(tid - 128) * DIM);
    char* dh = sm + ((tid < 128) ? OFF_AH : OFF_BH) + (tid & 127) * PITCH;
    char* dl = sm + ((tid < 128) ? OFF_AL : OFF_BL) + (tid & 127) * PITCH;

    // compute-role indices
    int warp_m = wid >> 2, warp_n = wid & 3;        // 2 x 4
    int g = lane >> 2, tig = lane & 3;              // group row, thread-in-group
    float acc[4][4][4] = {};                        // [mtile][ntile][frag]

    const char* pAh = sm + OFF_AH + (warp_m * 64 + g) * PITCH + tig * 4;
    const char* pAl = sm + OFF_AL + (warp_m * 64 + g) * PITCH + tig * 4;
    const char* pBh = sm + OFF_BH + (warp_n * 32 + g) * PITCH + tig * 4;
    const char* pBl = sm + OFF_BL + (warp_n * 32 + g) * PITCH + tig * 4;

    for (int c = 0; c < 32; ++c) {
        // ---- load + convert chunk c: 64 floats -> hi/lo bf16 ----
        const float4* s4 = (const float4*)(src + c * 64);
        #pragma unroll
        for (int i = 0; i < 16; i++) {
            float4 v = s4[i];
            __nv_bfloat16 h0 = __float2bfloat16_rn(v.x);
            __nv_bfloat16 h1 = __float2bfloat16_rn(v.y);
            __nv_bfloat16 h2 = __float2bfloat16_rn(v.z);
            __nv_bfloat16 h3 = __float2bfloat16_rn(v.w);
            __nv_bfloat16 l0 = __float2bfloat16_rn(v.x - __bfloat162float(h0));
            __nv_bfloat16 l1 = __float2bfloat16_rn(v.y - __bfloat162float(h1));
            __nv_bfloat16 l2 = __float2bfloat16_rn(v.z - __bfloat162float(h2));
            __nv_bfloat16 l3 = __float2bfloat16_rn(v.w - __bfloat162float(h3));
            uint2 hp, lp;
            hp.x = (uint32_t)__bfloat16_as_ushort(h0) | ((uint32_t)__bfloat16_as_ushort(h1) << 16);
            hp.y = (uint32_t)__bfloat16_as_ushort(h2) | ((uint32_t)__bfloat16_as_ushort(h3) << 16);
            lp.x = (uint32_t)__bfloat16_as_ushort(l0) | ((uint32_t)__bfloat16_as_ushort(l1) << 16);
            lp.y = (uint32_t)__bfloat16_as_ushort(l2) | ((uint32_t)__bfloat16_as_ushort(l3) << 16);
            *(uint2*)(dh + i * 8) = hp;
            *(uint2*)(dl + i * 8) = lp;
        }
        __syncthreads();

        // ---- compute: 4 k-steps of 16 ----
        #pragma unroll
        for (int ks = 0; ks < 4; ks++) {
            int kb = ks * 32;                       // 16 bf16 = 32 bytes
            uint32_t Ah[4][4], Al[4][4], Bh[4][2], Bl[4][2];
            #pragma unroll
            for (int i = 0; i < 4; i++) {
                const char* ph = pAh + i * 16 * PITCH + kb;
                const char* pl = pAl + i * 16 * PITCH + kb;
                Ah[i][0] = *(const uint32_t*)(ph);
                Ah[i][1] = *(const uint32_t*)(ph + 8 * PITCH);
                Ah[i][2] = *(const uint32_t*)(ph + 16);
                Ah[i][3] = *(const uint32_t*)(ph + 8 * PITCH + 16);
                Al[i][0] = *(const uint32_t*)(pl);
                Al[i][1] = *(const uint32_t*)(pl + 8 * PITCH);
                Al[i][2] = *(const uint32_t*)(pl + 16);
                Al[i][3] = *(const uint32_t*)(pl + 8 * PITCH + 16);
            }
            #pragma unroll
            for (int j = 0; j < 4; j++) {
                const char* ph = pBh + j * 8 * PITCH + kb;
                const char* pl = pBl + j * 8 * PITCH + kb;
                Bh[j][0] = *(const uint32_t*)(ph);
                Bh[j][1] = *(const uint32_t*)(ph + 16);
                Bl[j][0] = *(const uint32_t*)(pl);
                Bl[j][1] = *(const uint32_t*)(pl + 16);
            }
            #pragma unroll
            for (int i = 0; i < 4; i++)
                #pragma unroll
                for (int j = 0; j < 4; j++) {
                    mma16816(acc[i][j], Ah[i], Bh[j]);
                    mma16816(acc[i][j], Ah[i], Bl[j]);
                    mma16816(acc[i][j], Al[i], Bh[j]);
                }
        }
        __syncthreads();
    }

    // ---- epilogue: write C ----
    #pragma unroll
    for (int i = 0; i < 4; i++) {
        int r0 = mtile * 128 + warp_m * 64 + i * 16 + g;
        #pragma unroll
        for (int j = 0; j < 4; j++) {
            int col = ncol0 + warp_n * 32 + j * 8 + 2 * tig;
            *(float2*)&C[(size_t)r0 * ldc + col]       = make_float2(acc[i][j][0], acc[i][j][1]);
            *(float2*)&C[(size_t)(r0 + 8) * ldc + col] = make_float2(acc[i][j][2], acc[i][j][3]);
        }
    }
}

// ---------------- 4) per-head LN of q (from qv) and k1 ---------------------
__global__ void ln_heads(const float* __restrict__ qv, const float* __restrict__ k1,
                         const float* __restrict__ lw, const float* __restrict__ lb,
                         float* __restrict__ qn, float* __restrict__ k1n) {
    int gw   = (blockIdx.x * blockDim.x + threadIdx.x) >> 5;
    int lane = threadIdx.x & 31;
    if (gw >= 2 * B_SZ * NH) return;
    int r = gw & (B_SZ * NH - 1);
    int b = r >> 3, h = r & 7;
    const float* src;
    float* dst;
    if (gw < B_SZ * NH) { src = qv + (size_t)b * 2 * DIM + h * HD; dst = qn  + (size_t)b * DIM + h * HD; }
    else                { src = k1 + (size_t)b * DIM     + h * HD; dst = k1n + (size_t)b * DIM + h * HD; }

    float x[8], s = 0.f, ss = 0.f;
    #pragma unroll
    for (int j = 0; j < 8; j++) {
        x[j] = src[lane + 32 * j];
        s += x[j]; ss += x[j] * x[j];
    }
    s = warp_sum(s); ss = warp_sum(ss);
    float mu = s * (1.0f / HD);
    float inv = rsqrtf(ss * (1.0f / HD) - mu * mu + EPS);
    #pragma unroll
    for (int j = 0; j < 8; j++) {
        int i = lane + 32 * j;
        dst[i] = (x[j] - mu) * inv * lw[i] + lb[i];
    }
}

// ---------------- 5) fused: 2x attention + 2x conv1d + LNs + GELUs ---------
__global__ void __launch_bounds__(256, 4)
fused_attn(const float* __restrict__ qn, const float* __restrict__ k1n,
           const float* __restrict__ k2n, const float* __restrict__ qv,
           const float* __restrict__ lw, const float* __restrict__ lb,
           const float* __restrict__ l2w, const float* __restrict__ l2b,
           const float* __restrict__ w1, const float* __restrict__ w2,
           float* __restrict__ out) {
    __shared__ float sQ[DIM], sK1[DIM], sK2[DIM], sV[DIM], sO1[DIM];
    __shared__ float cw1[192], cw2[192];
    __shared__ float rs[8], rss[8];
    float* sO2 = sK1;

    int b = blockIdx.x, t = threadIdx.x;
    int wid = t >> 5, lane = t & 31;

    for (int i = t; i < DIM; i += 256) {
        sQ[i]  = qn[(size_t)b * DIM + i];
        sK1[i] = k1n[(size_t)b * DIM + i];
        sK2[i] = k2n[(size_t)b * DIM + i];
        sV[i]  = qv[(size_t)b * 2 * DIM + DIM + i];
    }
    if (t < 192) { cw1[t] = w1[t]; cw2[t] = w2[t]; }
    __syncthreads();

    {
        float a[8];
        #pragma unroll
        for (int s = 0; s < 8; s++) {
            float p = 0.f;
            #pragma unroll
            for (int j = 0; j < 8; j++)
                p = fmaf(sQ[wid * HD + lane + 32 * j], sK1[s * HD + lane + 32 * j], p);
            a[s] = warp_sum(p) * (1.0f / 16.0f);
        }
        float m = a[0];
        #pragma unroll
        for (int s = 1; s < 8; s++) m = fmaxf(m, a[s]);
        float sum = 0.f;
        #pragma unroll
        for (int s = 0; s < 8; s++) { a[s] = expf(a[s] - m); sum += a[s]; }
        float inv = 1.0f / sum;
        #pragma unroll
        for (int j = 0; j < 8; j++) {
            int cc = lane + 32 * j;
            float acc = 0.f;
            #pragma unroll
            for (int s = 0; s < 8; s++) acc = fmaf(a[s], sV[s * HD + cc], acc);
            sO1[wid * HD + cc] = acc * inv;
        }
    }
    __syncthreads();

    {
        float a[8];
        #pragma unroll
        for (int s = 0; s < 8; s++) {
            float p = 0.f;
            #pragma unroll
            for (int j = 0; j < 8; j++)
                p = fmaf(sQ[wid * HD + lane + 32 * j], sK2[s * HD + lane + 32 * j], p);
            a[s] = warp_sum(p) * (1.0f / 16.0f);
        }
        float m = a[0];
        #pragma unroll
        for (int s = 1; s < 8; s++) m = fmaxf(m, a[s]);
        float sum = 0.f;
        #pragma unroll
        for (int s = 0; s < 8; s++) { a[s] = expf(a[s] - m); sum += a[s]; }
        float inv = 1.0f / sum;
        #pragma unroll
        for (int j = 0; j < 8; j++) {
            int cc = lane + 32 * j;
            float acc = 0.f;
            #pragma unroll
            for (int s = 0; s < 8; s++) acc = fmaf(a[s], sV[s * HD + cc], acc);
            sO2[wid * HD + cc] = acc * inv;
        }
    }
    __syncthreads();

    float c1[8], c2[8], g[8];
    #pragma unroll
    for (int j = 0; j < 8; j++) {
        int l = lane + 32 * j;
        float a1 = 0.f, a2 = 0.f;
        #pragma unroll
        for (int i = 0; i < 8; i++) {
            float xm = (l > 0)   ? sO1[i * HD + l - 1] : 0.f;
            float x0 =             sO1[i * HD + l];
            float xp = (l < 255) ? sO1[i * HD + l + 1] : 0.f;
            a1 = fmaf(cw1[wid * 24 + i * 3 + 0], xm, a1);
            a1 = fmaf(cw1[wid * 24 + i * 3 + 1], x0, a1);
            a1 = fmaf(cw1[wid * 24 + i * 3 + 2], xp, a1);
            float ym = (l > 0)   ? sO2[i * HD + l - 1] : 0.f;
            float y0 =             sO2[i * HD + l];
            float yp = (l < 255) ? sO2[i * HD + l + 1] : 0.f;
            a2 = fmaf(cw2[wid * 24 + i * 3 + 0], ym, a2);
            a2 = fmaf(cw2[wid * 24 + i * 3 + 1], y0, a2);
            a2 = fmaf(cw2[wid * 24 + i * 3 + 2], yp, a2);
        }
        c1[j] = a1; c2[j] = a2;
    }

    {
        float s = 0.f, ss = 0.f;
        #pragma unroll
        for (int j = 0; j < 8; j++) { s += c1[j]; ss += c1[j] * c1[j]; }
        s = warp_sum(s); ss = warp_sum(ss);
        float mu = s * (1.0f / HD), inv = rsqrtf(ss * (1.0f / HD) - mu * mu + EPS);
        #pragma unroll
        for (int j = 0; j < 8; j++) { int i = lane + 32 * j; c1[j] = (c1[j] - mu) * inv * lw[i] + lb[i]; }
    }
    {
        float s = 0.f, ss = 0.f;
        #pragma unroll
        for (int j = 0; j < 8; j++) { s += c2[j]; ss += c2[j] * c2[j]; }
        s = warp_sum(s); ss = warp_sum(ss);
        float mu = s * (1.0f / HD), inv = rsqrtf(ss * (1.0f / HD) - mu * mu + EPS);
        #pragma unroll
        for (int j = 0; j < 8; j++) { int i = lane + 32 * j; c2[j] = (c2[j] - mu) * inv * lw[i] + lb[i]; }
    }
    {
        float x[8], s = 0.f, ss = 0.f;
        #pragma unroll
        for (int j = 0; j < 8; j++) {
            x[j] = c1[j] + c2[j] + sV[wid * HD + lane + 32 * j];
            s += x[j]; ss += x[j] * x[j];
        }
        s = warp_sum(s); ss = warp_sum(ss);
        float mu = s * (1.0f / HD), inv = rsqrtf(ss * (1.0f / HD) - mu * mu + EPS);
        #pragma unroll
        for (int j = 0; j < 8; j++) {
            int i = lane + 32 * j;
            g[j] = gelu_tanh((x[j] - mu) * inv * lw[i] + lb[i]);
        }
    }
    {
        float s = 0.f, ss = 0.f;
        #pragma unroll
        for (int j = 0; j < 8; j++) { s += g[j]; ss += g[j] * g[j]; }
        s = warp_sum(s); ss = warp_sum(ss);
        if (lane == 0) { rs[wid] = s; rss[wid] = ss; }
        __syncthreads();
        float ts = 0.f, tss = 0.f;
        #pragma unroll
        for (int i = 0; i < 8; i++) { ts += rs[i]; tss += rss[i]; }
        float mu = ts * (1.0f / DIM), inv = rsqrtf(tss * (1.0f / DIM) - mu * mu + EPS);
        #pragma unroll
        for (int j = 0; j < 8; j++) {
            int idx = wid * HD + lane + 32 * j;
            float y = (g[j] - mu) * inv * l2w[idx] + l2b[idx];
            out[(size_t)b * DIM + idx] = gelu_tanh(y);
        }
    }
}

// ---------------- launch ----------------
extern "C" void kernel_launch(void* const* d_in, const int* in_sizes, int n_in,
                              void* d_out, int out_size) {
    const float* f_ad    = (const float*)d_in[0];
    const float* f_age   = (const float*)d_in[1];
    const float* mem     = (const float*)d_in[2];
    const float* age_gap = (const float*)d_in[3];
    const float* qv_W    = (const float*)d_in[4];
    const float* k1_W    = (const float*)d_in[5];
    // d_in[6] = k2_W : dead in the reference — skipped
    const float* ln_w    = (const float*)d_in[7];
    const float* ln_b    = (const float*)d_in[8];
    const float* ln2_w   = (const float*)d_in[9];
    const float* ln2_b   = (const float*)d_in[10];
    const float* agf_rW  = (const float*)d_in[11];
    const float* agf_rb  = (const float*)d_in[12];
    const float* agf_eW  = (const float*)d_in[13];
    const float* agf_eb  = (const float*)d_in[14];
    const float* c1W     = (const float*)d_in[15];
    const float* c2W     = (const float*)d_in[16];
    float* out = (float*)d_out;

    float *pooled, *qvb, *k1b, *qn, *k1n, *k2n;
    cudaGetSymbolAddress((void**)&pooled, g_pooled);
    cudaGetSymbolAddress((void**)&qvb, g_qv);
    cudaGetSymbolAddress((void**)&k1b, g_k1);
    cudaGetSymbolAddress((void**)&qn, g_qn);
    cudaGetSymbolAddress((void**)&k1n, g_k1n);
    cudaGetSymbolAddress((void**)&k2n, g_k2n);

    cudaFuncSetAttribute(gemm_tc, cudaFuncAttributeMaxDynamicSharedMemorySize, GEMM_SMEM);

    pool_kernel<<<(B_SZ * DIM * 32) / 256, 256>>>(mem, pooled);
    agf_kernel<<<B_SZ, 256>>>(f_age, age_gap, agf_rW, agf_rb, agf_eW, agf_eb, ln_w, ln_b, k2n);
    gemm_tc<<<dim3(48, 2), 256, GEMM_SMEM>>>(f_ad, pooled, qv_W, k1_W, qvb, k1b);
    ln_heads<<<(2 * B_SZ * NH) / 8, 256>>>(qvb, k1b, ln_w, ln_b, qn, k1n);
    fused_attn<<<B_SZ, 256>>>(qn, k1n, k2n, qvb, ln_w, ln_b, ln2_w, ln2_b, c1W, c2W, out);
}

// round 4
// speedup vs baseline: 1.9700x; 1.2448x over previous
#include <cuda_runtime.h>
#include <cuda_bf16.h>
#include <math.h>
#include <stdint.h>

#define B_SZ 256
#define DIM 2048
#define NH 8
#define HD 256
#define EPS 1e-5f

// ---------------- scratch (device globals; no allocation allowed) ----------
__device__ float g_qv[B_SZ * 2 * DIM];
__device__ float g_k1[B_SZ * DIM];
__device__ float g_qn[B_SZ * DIM];
__device__ float g_k1n[B_SZ * DIM];
__device__ float g_k2n[B_SZ * DIM];
// split-bf16 (hi, lo) scratch
__device__ __nv_bfloat16 g_Wqvh[2 * DIM * DIM];
__device__ __nv_bfloat16 g_Wqvl[2 * DIM * DIM];
__device__ __nv_bfloat16 g_Wk1h[DIM * DIM];
__device__ __nv_bfloat16 g_Wk1l[DIM * DIM];
__device__ __nv_bfloat16 g_Ah[B_SZ * DIM];
__device__ __nv_bfloat16 g_Al[B_SZ * DIM];
__device__ __nv_bfloat16 g_Ph[B_SZ * DIM];
__device__ __nv_bfloat16 g_Pl[B_SZ * DIM];

// ---------------- helpers ----------------
__device__ __forceinline__ float warp_sum(float v) {
    v += __shfl_xor_sync(0xffffffffu, v, 16);
    v += __shfl_xor_sync(0xffffffffu, v, 8);
    v += __shfl_xor_sync(0xffffffffu, v, 4);
    v += __shfl_xor_sync(0xffffffffu, v, 2);
    v += __shfl_xor_sync(0xffffffffu, v, 1);
    return v;
}

__device__ __forceinline__ float gelu_tanh(float x) {
    const float k = 0.7978845608028654f;
    float x3 = x * x * x;
    return 0.5f * x * (1.0f + tanhf(k * (x + 0.044715f * x3)));
}

__device__ __forceinline__ uint32_t smem_u32(const void* p) {
    uint32_t a;
    asm("{ .reg .u64 t; cvta.to.shared.u64 t, %1; cvt.u32.u64 %0, t; }" : "=r"(a) : "l"(p));
    return a;
}

__device__ __forceinline__ void cpa16(uint32_t dst, const void* src) {
    asm volatile("cp.async.cg.shared.global [%0], [%1], 16;" :: "r"(dst), "l"(src));
}
#define CP_COMMIT() asm volatile("cp.async.commit_group;" ::: "memory")
#define CP_WAIT3()  asm volatile("cp.async.wait_group 3;" ::: "memory")

// bf16 mma: D(16x8,f32) += A(16x16,bf16) * B(16x8,bf16)
__device__ __forceinline__ void mma16816(float* d, const uint32_t* a, const uint32_t* b) {
    asm volatile(
        "mma.sync.aligned.m16n8k16.row.col.f32.bf16.bf16.f32 "
        "{%0,%1,%2,%3}, {%4,%5,%6,%7}, {%8,%9}, {%0,%1,%2,%3};"
        : "+f"(d[0]), "+f"(d[1]), "+f"(d[2]), "+f"(d[3])
        : "r"(a[0]), "r"(a[1]), "r"(a[2]), "r"(a[3]), "r"(b[0]), "r"(b[1]));
}

// ---------------- 0) fp32 -> (hi, lo) bf16 split ---------------------------
__global__ void convert_split(const float4* __restrict__ src,
                              uint2* __restrict__ hi, uint2* __restrict__ lo, int n4) {
    int i = blockIdx.x * blockDim.x + threadIdx.x;
    if (i >= n4) return;
    float4 v = src[i];
    __nv_bfloat16 h0 = __float2bfloat16_rn(v.x);
    __nv_bfloat16 h1 = __float2bfloat16_rn(v.y);
    __nv_bfloat16 h2 = __float2bfloat16_rn(v.z);
    __nv_bfloat16 h3 = __float2bfloat16_rn(v.w);
    __nv_bfloat16 l0 = __float2bfloat16_rn(v.x - __bfloat162float(h0));
    __nv_bfloat16 l1 = __float2bfloat16_rn(v.y - __bfloat162float(h1));
    __nv_bfloat16 l2 = __float2bfloat16_rn(v.z - __bfloat162float(h2));
    __nv_bfloat16 l3 = __float2bfloat16_rn(v.w - __bfloat162float(h3));
    uint2 hp, lp;
    hp.x = (uint32_t)__bfloat16_as_ushort(h0) | ((uint32_t)__bfloat16_as_ushort(h1) << 16);
    hp.y = (uint32_t)__bfloat16_as_ushort(h2) | ((uint32_t)__bfloat16_as_ushort(h3) << 16);
    lp.x = (uint32_t)__bfloat16_as_ushort(l0) | ((uint32_t)__bfloat16_as_ushort(l1) << 16);
    lp.y = (uint32_t)__bfloat16_as_ushort(l2) | ((uint32_t)__bfloat16_as_ushort(l3) << 16);
    hi[i] = hp;
    lo[i] = lp;
}

// ---------------- 1) mean-pool mem; emit (hi, lo) bf16 ---------------------
__global__ void pool_kernel(const float* __restrict__ mem,
                            __nv_bfloat16* __restrict__ ph, __nv_bfloat16* __restrict__ pl) {
    int gw   = (blockIdx.x * blockDim.x + threadIdx.x) >> 5;
    int lane = threadIdx.x & 31;
    if (gw >= B_SZ * DIM) return;
    const float2 v = *(const float2*)&mem[(size_t)gw * 64 + lane * 2];
    float s = warp_sum(v.x + v.y);
    if (lane == 0) {
        float m = s * (1.0f / 64.0f);
        __nv_bfloat16 h = __float2bfloat16_rn(m);
        ph[gw] = h;
        pl[gw] = __float2bfloat16_rn(m - __bfloat162float(h));
    }
}

// ---------------- 2) AGF branch + per-head LN -> k2_norm -------------------
__global__ void agf_kernel(const float* __restrict__ f_age, const float* __restrict__ age_gap,
                           const float* __restrict__ rW, const float* __restrict__ rb,
                           const float* __restrict__ eW, const float* __restrict__ eb,
                           const float* __restrict__ lw, const float* __restrict__ lb,
                           float* __restrict__ k2n) {
    __shared__ float srow[DIM];
    __shared__ float pr[8];
    int b = blockIdx.x, t = threadIdx.x;
    int wid = t >> 5, lane = t & 31;

    float part = 0.f;
    for (int i = t; i < DIM; i += 256) part += f_age[(size_t)b * DIM + i] * rW[i];
    part = warp_sum(part);
    if (lane == 0) pr[wid] = part;
    __syncthreads();
    float red = rb[0];
    #pragma unroll
    for (int i = 0; i < 8; i++) red += pr[i];
    float ag = age_gap[b];

    for (int i = t; i < DIM; i += 256) {
        srow[i] = f_age[(size_t)b * DIM + i] + eW[i * 2 + 0] * red + eW[i * 2 + 1] * ag + eb[i];
    }
    __syncthreads();

    float x[8], s = 0.f, ss = 0.f;
    #pragma unroll
    for (int j = 0; j < 8; j++) {
        x[j] = srow[wid * HD + lane + 32 * j];
        s += x[j]; ss += x[j] * x[j];
    }
    s = warp_sum(s); ss = warp_sum(ss);
    float mu = s * (1.0f / HD);
    float inv = rsqrtf(ss * (1.0f / HD) - mu * mu + EPS);
    #pragma unroll
    for (int j = 0; j < 8; j++) {
        int i = lane + 32 * j;
        k2n[(size_t)b * DIM + wid * HD + i] = (x[j] - mu) * inv * lw[i] + lb[i];
    }
}

// ---------------- 3) tensor-core GEMM, cp.async 4-stage pipeline -----------
// C[m,n] = sum_k A[m,k]*W[n,k];  D += Ah*Bh + Ah*Bl + Al*Bh  (fp32 accum)
// CTA tile M=128 N=128; K chunks of 32 (2 k-steps). 8 warps 2x4, warp 64x32.
#define CHUNKS 64
#define PITCH 80                        // 64B data + 16B pad; banks (20g+tig)%32 unique
#define TILEB (128 * PITCH)             // 10240
#define NSTAGE 4
#define STAGEB (4 * TILEB)              // Ah Al Bh Bl
#define GEMM_SMEM (NSTAGE * STAGEB)     // 163840

__global__ void __launch_bounds__(256, 1)
gemm_tc(const __nv_bfloat16* __restrict__ Ah, const __nv_bfloat16* __restrict__ Al,
        const __nv_bfloat16* __restrict__ Ph, const __nv_bfloat16* __restrict__ Pl,
        const __nv_bfloat16* __restrict__ Wqh, const __nv_bfloat16* __restrict__ Wql,
        const __nv_bfloat16* __restrict__ Wkh, const __nv_bfloat16* __restrict__ Wkl,
        float* __restrict__ Cqv, float* __restrict__ Ck1) {
    extern __shared__ char sm[];
    uint32_t sb = smem_u32(sm);
    int tid = threadIdx.x, wid = tid >> 5, lane = tid & 31;
    int ntile = blockIdx.x, mtile = blockIdx.y;

    bool is_qv = ntile < 32;
    const __nv_bfloat16 *ah, *al, *bh, *bl;
    float* C;
    int ldc, ncol0;
    if (is_qv) {
        ah = Ah; al = Al;
        bh = Wqh + (size_t)ntile * 128 * DIM; bl = Wql + (size_t)ntile * 128 * DIM;
        C = Cqv; ldc = 2 * DIM; ncol0 = ntile * 128;
    } else {
        ah = Ph; al = Pl;
        bh = Wkh + (size_t)(ntile - 32) * 128 * DIM; bl = Wkl + (size_t)(ntile - 32) * 128 * DIM;
        C = Ck1; ldc = DIM; ncol0 = (ntile - 32) * 128;
    }

    // loader role: row r, byte-quarter q (0 or 32) of the 64B chunk row
    int r = tid >> 1, q = (tid & 1) * 32;
    const char* sAh = (const char*)(ah + (size_t)(mtile * 128 + r) * DIM) + q;
    const char* sAl = (const char*)(al + (size_t)(mtile * 128 + r) * DIM) + q;
    const char* sBh = (const char*)(bh + (size_t)r * DIM) + q;
    const char* sBl = (const char*)(bl + (size_t)r * DIM) + q;
    uint32_t dbase = sb + r * PITCH + q;

    // compute role
    int warp_m = wid >> 2, warp_n = wid & 3;
    int g = lane >> 2, tig = lane & 3;
    float acc[4][4][4] = {};
    uint32_t fA_h = sb + (warp_m * 64 + g) * PITCH + tig * 4;
    uint32_t fA_l = fA_h + TILEB;
    uint32_t fB_h = sb + 2 * TILEB + (warp_n * 32 + g) * PITCH + tig * 4;
    uint32_t fB_l = fB_h + TILEB;

    // prologue: fill 4 stages
    #pragma unroll
    for (int s = 0; s < NSTAGE; s++) {
        uint32_t d = dbase + s * STAGEB;
        cpa16(d,              sAh + s * 64); cpa16(d + 16,              sAh + s * 64 + 16);
        cpa16(d + TILEB,      sAl + s * 64); cpa16(d + TILEB + 16,      sAl + s * 64 + 16);
        cpa16(d + 2 * TILEB,  sBh + s * 64); cpa16(d + 2 * TILEB + 16,  sBh + s * 64 + 16);
        cpa16(d + 3 * TILEB,  sBl + s * 64); cpa16(d + 3 * TILEB + 16,  sBl + s * 64 + 16);
        CP_COMMIT();
    }

    for (int c = 0; c < CHUNKS; ++c) {
        int s = c & (NSTAGE - 1);
        uint32_t so = (uint32_t)s * STAGEB;
        CP_WAIT3();
        __syncthreads();

        #pragma unroll
        for (int ks = 0; ks < 2; ks++) {
            uint32_t kb = so + ks * 32;
            uint32_t Ahf[4][4], Alf[4][4], Bhf[4][2], Blf[4][2];
            #pragma unroll
            for (int i = 0; i < 4; i++) {
                uint32_t ph = fA_h + i * 16 * PITCH + kb;
                uint32_t pl = fA_l + i * 16 * PITCH + kb;
                asm volatile("ld.shared.b32 %0, [%1];" : "=r"(Ahf[i][0]) : "r"(ph));
                asm volatile("ld.shared.b32 %0, [%1];" : "=r"(Ahf[i][1]) : "r"(ph + 8 * PITCH));
                asm volatile("ld.shared.b32 %0, [%1];" : "=r"(Ahf[i][2]) : "r"(ph + 16));
                asm volatile("ld.shared.b32 %0, [%1];" : "=r"(Ahf[i][3]) : "r"(ph + 8 * PITCH + 16));
                asm volatile("ld.shared.b32 %0, [%1];" : "=r"(Alf[i][0]) : "r"(pl));
                asm volatile("ld.shared.b32 %0, [%1];" : "=r"(Alf[i][1]) : "r"(pl + 8 * PITCH));
                asm volatile("ld.shared.b32 %0, [%1];" : "=r"(Alf[i][2]) : "r"(pl + 16));
                asm volatile("ld.shared.b32 %0, [%1];" : "=r"(Alf[i][3]) : "r"(pl + 8 * PITCH + 16));
            }
            #pragma unroll
            for (int j = 0; j < 4; j++) {
                uint32_t ph = fB_h + j * 8 * PITCH + kb;
                uint32_t pl = fB_l + j * 8 * PITCH + kb;
                asm volatile("ld.shared.b32 %0, [%1];" : "=r"(Bhf[j][0]) : "r"(ph));
                asm volatile("ld.shared.b32 %0, [%1];" : "=r"(Bhf[j][1]) : "r"(ph + 16));
                asm volatile("ld.shared.b32 %0, [%1];" : "=r"(Blf[j][0]) : "r"(pl));
                asm volatile("ld.shared.b32 %0, [%1];" : "=r"(Blf[j][1]) : "r"(pl + 16));
            }
            #pragma unroll
            for (int i = 0; i < 4; i++)
                #pragma unroll
                for (int j = 0; j < 4; j++) {
                    mma16816(acc[i][j], Ahf[i], Bhf[j]);
                    mma16816(acc[i][j], Ahf[i], Blf[j]);
                    mma16816(acc[i][j], Alf[i], Bhf[j]);
                }
        }
        __syncthreads();

        int cn = c + NSTAGE;
        if (cn < CHUNKS) {
            uint32_t d = dbase + so;
            cpa16(d,             sAh + cn * 64); cpa16(d + 16,             sAh + cn * 64 + 16);
            cpa16(d + TILEB,     sAl + cn * 64); cpa16(d + TILEB + 16,     sAl + cn * 64 + 16);
            cpa16(d + 2 * TILEB, sBh + cn * 64); cpa16(d + 2 * TILEB + 16, sBh + cn * 64 + 16);
            cpa16(d + 3 * TILEB, sBl + cn * 64); cpa16(d + 3 * TILEB + 16, sBl + cn * 64 + 16);
        }
        CP_COMMIT();
    }

    // epilogue
    #pragma unroll
    for (int i = 0; i < 4; i++) {
        int r0 = mtile * 128 + warp_m * 64 + i * 16 + g;
        #pragma unroll
        for (int j = 0; j < 4; j++) {
            int col = ncol0 + warp_n * 32 + j * 8 + 2 * tig;
            *(float2*)&C[(size_t)r0 * ldc + col]       = make_float2(acc[i][j][0], acc[i][j][1]);
            *(float2*)&C[(size_t)(r0 + 8) * ldc + col] = make_float2(acc[i][j][2], acc[i][j][3]);
        }
    }
}

// ---------------- 4) per-head LN of q (from qv) and k1 ---------------------
__global__ void ln_heads(const float* __restrict__ qv, const float* __restrict__ k1,
                         const float* __restrict__ lw, const float* __restrict__ lb,
                         float* __restrict__ qn, float* __restrict__ k1n) {
    int gw   = (blockIdx.x * blockDim.x + threadIdx.x) >> 5;
    int lane = threadIdx.x & 31;
    if (gw >= 2 * B_SZ * NH) return;
    int r = gw & (B_SZ * NH - 1);
    int b = r >> 3, h = r & 7;
    const float* src;
    float* dst;
    if (gw < B_SZ * NH) { src = qv + (size_t)b * 2 * DIM + h * HD; dst = qn  + (size_t)b * DIM + h * HD; }
    else                { src = k1 + (size_t)b * DIM     + h * HD; dst = k1n + (size_t)b * DIM + h * HD; }

    float x[8], s = 0.f, ss = 0.f;
    #pragma unroll
    for (int j = 0; j < 8; j++) {
        x[j] = src[lane + 32 * j];
        s += x[j]; ss += x[j] * x[j];
    }
    s = warp_sum(s); ss = warp_sum(ss);
    float mu = s * (1.0f / HD);
    float inv = rsqrtf(ss * (1.0f / HD) - mu * mu + EPS);
    #pragma unroll
    for (int j = 0; j < 8; j++) {
        int i = lane + 32 * j;
        dst[i] = (x[j] - mu) * inv * lw[i] + lb[i];
    }
}

// ---------------- 5) fused: 2x attention + 2x conv1d + LNs + GELUs ---------
__global__ void __launch_bounds__(256, 4)
fused_attn(const float* __restrict__ qn, const float* __restrict__ k1n,
           const float* __restrict__ k2n, const float* __restrict__ qv,
           const float* __restrict__ lw, const float* __restrict__ lb,
           const float* __restrict__ l2w, const float* __restrict__ l2b,
           const float* __restrict__ w1, const float* __restrict__ w2,
           float* __restrict__ out) {
    __shared__ float sQ[DIM], sK1[DIM], sK2[DIM], sV[DIM], sO1[DIM];
    __shared__ float cw1[192], cw2[192];
    __shared__ float rs[8], rss[8];
    float* sO2 = sK1;

    int b = blockIdx.x, t = threadIdx.x;
    int wid = t >> 5, lane = t & 31;

    for (int i = t; i < DIM; i += 256) {
        sQ[i]  = qn[(size_t)b * DIM + i];
        sK1[i] = k1n[(size_t)b * DIM + i];
        sK2[i] = k2n[(size_t)b * DIM + i];
        sV[i]  = qv[(size_t)b * 2 * DIM + DIM + i];
    }
    if (t < 192) { cw1[t] = w1[t]; cw2[t] = w2[t]; }
    __syncthreads();

    {
        float a[8];
        #pragma unroll
        for (int s = 0; s < 8; s++) {
            float p = 0.f;
            #pragma unroll
            for (int j = 0; j < 8; j++)
                p = fmaf(sQ[wid * HD + lane + 32 * j], sK1[s * HD + lane + 32 * j], p);
            a[s] = warp_sum(p) * (1.0f / 16.0f);
        }
        float m = a[0];
        #pragma unroll
        for (int s = 1; s < 8; s++) m = fmaxf(m, a[s]);
        float sum = 0.f;
        #pragma unroll
        for (int s = 0; s < 8; s++) { a[s] = expf(a[s] - m); sum += a[s]; }
        float inv = 1.0f / sum;
        #pragma unroll
        for (int j = 0; j < 8; j++) {
            int cc = lane + 32 * j;
            float acc = 0.f;
            #pragma unroll
            for (int s = 0; s < 8; s++) acc = fmaf(a[s], sV[s * HD + cc], acc);
            sO1[wid * HD + cc] = acc * inv;
        }
    }
    __syncthreads();

    {
        float a[8];
        #pragma unroll
        for (int s = 0; s < 8; s++) {
            float p = 0.f;
            #pragma unroll
            for (int j = 0; j < 8; j++)
                p = fmaf(sQ[wid * HD + lane + 32 * j], sK2[s * HD + lane + 32 * j], p);
            a[s] = warp_sum(p) * (1.0f / 16.0f);
        }
        float m = a[0];
        #pragma unroll
        for (int s = 1; s < 8; s++) m = fmaxf(m, a[s]);
        float sum = 0.f;
        #pragma unroll
        for (int s = 0; s < 8; s++) { a[s] = expf(a[s] - m); sum += a[s]; }
        float inv = 1.0f / sum;
        #pragma unroll
        for (int j = 0; j < 8; j++) {
            int cc = lane + 32 * j;
            float acc = 0.f;
            #pragma unroll
            for (int s = 0; s < 8; s++) acc = fmaf(a[s], sV[s * HD + cc], acc);
            sO2[wid * HD + cc] = acc * inv;
        }
    }
    __syncthreads();

    float c1[8], c2[8], g[8];
    #pragma unroll
    for (int j = 0; j < 8; j++) {
        int l = lane + 32 * j;
        float a1 = 0.f, a2 = 0.f;
        #pragma unroll
        for (int i = 0; i < 8; i++) {
            float xm = (l > 0)   ? sO1[i * HD + l - 1] : 0.f;
            float x0 =             sO1[i * HD + l];
            float xp = (l < 255) ? sO1[i * HD + l + 1] : 0.f;
            a1 = fmaf(cw1[wid * 24 + i * 3 + 0], xm, a1);
            a1 = fmaf(cw1[wid * 24 + i * 3 + 1], x0, a1);
            a1 = fmaf(cw1[wid * 24 + i * 3 + 2], xp, a1);
            float ym = (l > 0)   ? sO2[i * HD + l - 1] : 0.f;
            float y0 =             sO2[i * HD + l];
            float yp = (l < 255) ? sO2[i * HD + l + 1] : 0.f;
            a2 = fmaf(cw2[wid * 24 + i * 3 + 0], ym, a2);
            a2 = fmaf(cw2[wid * 24 + i * 3 + 1], y0, a2);
            a2 = fmaf(cw2[wid * 24 + i * 3 + 2], yp, a2);
        }
        c1[j] = a1; c2[j] = a2;
    }

    {
        float s = 0.f, ss = 0.f;
        #pragma unroll
        for (int j = 0; j < 8; j++) { s += c1[j]; ss += c1[j] * c1[j]; }
        s = warp_sum(s); ss = warp_sum(ss);
        float mu = s * (1.0f / HD), inv = rsqrtf(ss * (1.0f / HD) - mu * mu + EPS);
        #pragma unroll
        for (int j = 0; j < 8; j++) { int i = lane + 32 * j; c1[j] = (c1[j] - mu) * inv * lw[i] + lb[i]; }
    }
    {
        float s = 0.f, ss = 0.f;
        #pragma unroll
        for (int j = 0; j < 8; j++) { s += c2[j]; ss += c2[j] * c2[j]; }
        s = warp_sum(s); ss = warp_sum(ss);
        float mu = s * (1.0f / HD), inv = rsqrtf(ss * (1.0f / HD) - mu * mu + EPS);
        #pragma unroll
        for (int j = 0; j < 8; j++) { int i = lane + 32 * j; c2[j] = (c2[j] - mu) * inv * lw[i] + lb[i]; }
    }
    {
        float x[8], s = 0.f, ss = 0.f;
        #pragma unroll
        for (int j = 0; j < 8; j++) {
            x[j] = c1[j] + c2[j] + sV[wid * HD + lane + 32 * j];
            s += x[j]; ss += x[j] * x[j];
        }
        s = warp_sum(s); ss = warp_sum(ss);
        float mu = s * (1.0f / HD), inv = rsqrtf(ss * (1.0f / HD) - mu * mu + EPS);
        #pragma unroll
        for (int j = 0; j < 8; j++) {
            int i = lane + 32 * j;
            g[j] = gelu_tanh((x[j] - mu) * inv * lw[i] + lb[i]);
        }
    }
    {
        float s = 0.f, ss = 0.f;
        #pragma unroll
        for (int j = 0; j < 8; j++) { s += g[j]; ss += g[j] * g[j]; }
        s = warp_sum(s); ss = warp_sum(ss);
        if (lane == 0) { rs[wid] = s; rss[wid] = ss; }
        __syncthreads();
        float ts = 0.f, tss = 0.f;
        #pragma unroll
        for (int i = 0; i < 8; i++) { ts += rs[i]; tss += rss[i]; }
        float mu = ts * (1.0f / DIM), inv = rsqrtf(tss * (1.0f / DIM) - mu * mu + EPS);
        #pragma unroll
        for (int j = 0; j < 8; j++) {
            int idx = wid * HD + lane + 32 * j;
            float y = (g[j] - mu) * inv * l2w[idx] + l2b[idx];
            out[(size_t)b * DIM + idx] = gelu_tanh(y);
        }
    }
}

// ---------------- launch ----------------
extern "C" void kernel_launch(void* const* d_in, const int* in_sizes, int n_in,
                              void* d_out, int out_size) {
    const float* f_ad    = (const float*)d_in[0];
    const float* f_age   = (const float*)d_in[1];
    const float* mem     = (const float*)d_in[2];
    const float* age_gap = (const float*)d_in[3];
    const float* qv_W    = (const float*)d_in[4];
    const float* k1_W    = (const float*)d_in[5];
    // d_in[6] = k2_W : dead in the reference — skipped
    const float* ln_w    = (const float*)d_in[7];
    const float* ln_b    = (const float*)d_in[8];
    const float* ln2_w   = (const float*)d_in[9];
    const float* ln2_b   = (const float*)d_in[10];
    const float* agf_rW  = (const float*)d_in[11];
    const float* agf_rb  = (const float*)d_in[12];
    const float* agf_eW  = (const float*)d_in[13];
    const float* agf_eb  = (const float*)d_in[14];
    const float* c1W     = (const float*)d_in[15];
    const float* c2W     = (const float*)d_in[16];
    float* out = (float*)d_out;

    float *qvb, *k1b, *qn, *k1n, *k2n;
    __nv_bfloat16 *Wqh, *Wql, *Wkh, *Wkl, *Ahp, *Alp, *Php, *Plp;
    cudaGetSymbolAddress((void**)&qvb, g_qv);
    cudaGetSymbolAddress((void**)&k1b, g_k1);
    cudaGetSymbolAddress((void**)&qn, g_qn);
    cudaGetSymbolAddress((void**)&k1n, g_k1n);
    cudaGetSymbolAddress((void**)&k2n, g_k2n);
    cudaGetSymbolAddress((void**)&Wqh, g_Wqvh);
    cudaGetSymbolAddress((void**)&Wql, g_Wqvl);
    cudaGetSymbolAddress((void**)&Wkh, g_Wk1h);
    cudaGetSymbolAddress((void**)&Wkl, g_Wk1l);
    cudaGetSymbolAddress((void**)&Ahp, g_Ah);
    cudaGetSymbolAddress((void**)&Alp, g_Al);
    cudaGetSymbolAddress((void**)&Php, g_Ph);
    cudaGetSymbolAddress((void**)&Plp, g_Pl);

    cudaFuncSetAttribute(gemm_tc, cudaFuncAttributeMaxDynamicSharedMemorySize, GEMM_SMEM);

    // pool mem -> pooled (hi, lo)
    pool_kernel<<<(B_SZ * DIM * 32) / 256, 256>>>(mem, Php, Plp);
    // split weights + f_ad
    convert_split<<<(2 * DIM * DIM / 4 + 255) / 256, 256>>>(
        (const float4*)qv_W, (uint2*)Wqh, (uint2*)Wql, 2 * DIM * DIM / 4);
    convert_split<<<(DIM * DIM / 4 + 255) / 256, 256>>>(
        (const float4*)k1_W, (uint2*)Wkh, (uint2*)Wkl, DIM * DIM / 4);
    convert_split<<<(B_SZ * DIM / 4 + 255) / 256, 256>>>(
        (const float4*)f_ad, (uint2*)Ahp, (uint2*)Alp, B_SZ * DIM / 4);
    // AGF branch
    agf_kernel<<<B_SZ, 256>>>(f_age, age_gap, agf_rW, agf_rb, agf_eW, agf_eb, ln_w, ln_b, k2n);
    // tensor-core GEMMs
    gemm_tc<<<dim3(48, 2), 256, GEMM_SMEM>>>(Ahp, Alp, Php, Plp, Wqh, Wql, Wkh, Wkl, qvb, k1b);
    // per-head LN
    ln_heads<<<(2 * B_SZ * NH) / 8, 256>>>(qvb, k1b, ln_w, ln_b, qn, k1n);
    // fused attention + conv + epilogue
    fused_attn<<<B_SZ, 256>>>(qn, k1n, k2n, qvb, ln_w, ln_b, ln2_w, ln2_b, c1W, c2W, out);
}

// round 5
// speedup vs baseline: 2.3741x; 1.2051x over previous
#include <cuda_runtime.h>
#include <cuda_bf16.h>
#include <cuda_fp16.h>
#include <math.h>
#include <stdint.h>

#define B_SZ 256
#define DIM 2048
#define NH 8
#define HD 256
#define EPS 1e-5f

// ---------------- scratch (device globals; no allocation allowed) ----------
__device__ float g_qv[B_SZ * 2 * DIM];
__device__ float g_k1[B_SZ * DIM];
__device__ float g_qn[B_SZ * DIM];
__device__ float g_k1n[B_SZ * DIM];
__device__ float g_k2n[B_SZ * DIM];
// fp16 scratch: A split exact (hi+lo), weights hi-only
__device__ __half g_Wqvh[2 * DIM * DIM];
__device__ __half g_Wk1h[DIM * DIM];
__device__ __half g_Ah[B_SZ * DIM];
__device__ __half g_Al[B_SZ * DIM];
__device__ __half g_Ph[B_SZ * DIM];
__device__ __half g_Pl[B_SZ * DIM];

// ---------------- helpers ----------------
__device__ __forceinline__ float warp_sum(float v) {
    v += __shfl_xor_sync(0xffffffffu, v, 16);
    v += __shfl_xor_sync(0xffffffffu, v, 8);
    v += __shfl_xor_sync(0xffffffffu, v, 4);
    v += __shfl_xor_sync(0xffffffffu, v, 2);
    v += __shfl_xor_sync(0xffffffffu, v, 1);
    return v;
}

__device__ __forceinline__ float gelu_tanh(float x) {
    const float k = 0.7978845608028654f;
    float x3 = x * x * x;
    return 0.5f * x * (1.0f + tanhf(k * (x + 0.044715f * x3)));
}

__device__ __forceinline__ uint32_t smem_u32(const void* p) {
    uint32_t a;
    asm("{ .reg .u64 t; cvta.to.shared.u64 t, %1; cvt.u32.u64 %0, t; }" : "=r"(a) : "l"(p));
    return a;
}

__device__ __forceinline__ void cpa16(uint32_t dst, const void* src) {
    asm volatile("cp.async.cg.shared.global [%0], [%1], 16;" :: "r"(dst), "l"(src));
}
#define CP_COMMIT() asm volatile("cp.async.commit_group;" ::: "memory")
#define CP_WAIT3()  asm volatile("cp.async.wait_group 3;" ::: "memory")

// fp16 mma: D(16x8,f32) += A(16x16,f16) * B(16x8,f16)
__device__ __forceinline__ void mma16816f(float* d, const uint32_t* a, const uint32_t* b) {
    asm volatile(
        "mma.sync.aligned.m16n8k16.row.col.f32.f16.f16.f32 "
        "{%0,%1,%2,%3}, {%4,%5,%6,%7}, {%8,%9}, {%0,%1,%2,%3};"
        : "+f"(d[0]), "+f"(d[1]), "+f"(d[2]), "+f"(d[3])
        : "r"(a[0]), "r"(a[1]), "r"(a[2]), "r"(a[3]), "r"(b[0]), "r"(b[1]));
}

// ---------------- 0a) fp32 -> fp16 hi only (weights) -----------------------
__global__ void convert_hi(const float4* __restrict__ src, uint2* __restrict__ hi, int n4) {
    int i = blockIdx.x * blockDim.x + threadIdx.x;
    if (i >= n4) return;
    float4 v = src[i];
    __half h0 = __float2half_rn(v.x), h1 = __float2half_rn(v.y);
    __half h2 = __float2half_rn(v.z), h3 = __float2half_rn(v.w);
    uint2 hp;
    hp.x = (uint32_t)__half_as_ushort(h0) | ((uint32_t)__half_as_ushort(h1) << 16);
    hp.y = (uint32_t)__half_as_ushort(h2) | ((uint32_t)__half_as_ushort(h3) << 16);
    hi[i] = hp;
}

// ---------------- 0b) fp32 -> fp16 exact split (A matrices) ----------------
__global__ void convert_split(const float4* __restrict__ src,
                              uint2* __restrict__ hi, uint2* __restrict__ lo, int n4) {
    int i = blockIdx.x * blockDim.x + threadIdx.x;
    if (i >= n4) return;
    float4 v = src[i];
    __half h0 = __float2half_rn(v.x), h1 = __float2half_rn(v.y);
    __half h2 = __float2half_rn(v.z), h3 = __float2half_rn(v.w);
    __half l0 = __float2half_rn(v.x - __half2float(h0));
    __half l1 = __float2half_rn(v.y - __half2float(h1));
    __half l2 = __float2half_rn(v.z - __half2float(h2));
    __half l3 = __float2half_rn(v.w - __half2float(h3));
    uint2 hp, lp;
    hp.x = (uint32_t)__half_as_ushort(h0) | ((uint32_t)__half_as_ushort(h1) << 16);
    hp.y = (uint32_t)__half_as_ushort(h2) | ((uint32_t)__half_as_ushort(h3) << 16);
    lp.x = (uint32_t)__half_as_ushort(l0) | ((uint32_t)__half_as_ushort(l1) << 16);
    lp.y = (uint32_t)__half_as_ushort(l2) | ((uint32_t)__half_as_ushort(l3) << 16);
    hi[i] = hp;
    lo[i] = lp;
}

// ---------------- 1) mean-pool mem; emit fp16 (hi, lo) ---------------------
__global__ void pool_kernel(const float* __restrict__ mem,
                            __half* __restrict__ ph, __half* __restrict__ pl) {
    int gw   = (blockIdx.x * blockDim.x + threadIdx.x) >> 5;
    int lane = threadIdx.x & 31;
    if (gw >= B_SZ * DIM) return;
    const float2 v = *(const float2*)&mem[(size_t)gw * 64 + lane * 2];
    float s = warp_sum(v.x + v.y);
    if (lane == 0) {
        float m = s * (1.0f / 64.0f);
        __half h = __float2half_rn(m);
        ph[gw] = h;
        pl[gw] = __float2half_rn(m - __half2float(h));
    }
}

// ---------------- 2) AGF branch + per-head LN -> k2_norm -------------------
__global__ void agf_kernel(const float* __restrict__ f_age, const float* __restrict__ age_gap,
                           const float* __restrict__ rW, const float* __restrict__ rb,
                           const float* __restrict__ eW, const float* __restrict__ eb,
                           const float* __restrict__ lw, const float* __restrict__ lb,
                           float* __restrict__ k2n) {
    __shared__ float srow[DIM];
    __shared__ float pr[8];
    int b = blockIdx.x, t = threadIdx.x;
    int wid = t >> 5, lane = t & 31;

    float part = 0.f;
    for (int i = t; i < DIM; i += 256) part += f_age[(size_t)b * DIM + i] * rW[i];
    part = warp_sum(part);
    if (lane == 0) pr[wid] = part;
    __syncthreads();
    float red = rb[0];
    #pragma unroll
    for (int i = 0; i < 8; i++) red += pr[i];
    float ag = age_gap[b];

    for (int i = t; i < DIM; i += 256) {
        srow[i] = f_age[(size_t)b * DIM + i] + eW[i * 2 + 0] * red + eW[i * 2 + 1] * ag + eb[i];
    }
    __syncthreads();

    float x[8], s = 0.f, ss = 0.f;
    #pragma unroll
    for (int j = 0; j < 8; j++) {
        x[j] = srow[wid * HD + lane + 32 * j];
        s += x[j]; ss += x[j] * x[j];
    }
    s = warp_sum(s); ss = warp_sum(ss);
    float mu = s * (1.0f / HD);
    float inv = rsqrtf(ss * (1.0f / HD) - mu * mu + EPS);
    #pragma unroll
    for (int j = 0; j < 8; j++) {
        int i = lane + 32 * j;
        k2n[(size_t)b * DIM + wid * HD + i] = (x[j] - mu) * inv * lw[i] + lb[i];
    }
}

// ---------------- 3) tensor-core GEMM, fp16 2-term, cp.async 4-stage -------
// C[m,n] = sum_k A[m,k]*W[n,k];  D += Ah*Bh + Al*Bh = A*Bh  (fp32 accum)
// CTA tile M=128 N=128; K chunks of 32 (2 k-steps). 8 warps 2x4, warp 64x32.
#define CHUNKS 64
#define PITCH 80                        // 64B data + 16B pad; conflict-free frag banks
#define TILEB (128 * PITCH)             // 10240
#define NSTAGE 4
#define STAGEB (3 * TILEB)              // Ah Al Bh
#define GEMM_SMEM (NSTAGE * STAGEB)     // 122880

__global__ void __launch_bounds__(256, 1)
gemm_tc(const __half* __restrict__ Ah, const __half* __restrict__ Al,
        const __half* __restrict__ Ph, const __half* __restrict__ Pl,
        const __half* __restrict__ Wqh, const __half* __restrict__ Wkh,
        float* __restrict__ Cqv, float* __restrict__ Ck1) {
    extern __shared__ char sm[];
    uint32_t sb = smem_u32(sm);
    int tid = threadIdx.x, wid = tid >> 5, lane = tid & 31;
    int ntile = blockIdx.x, mtile = blockIdx.y;

    bool is_qv = ntile < 32;
    const __half *ah, *al, *bh;
    float* C;
    int ldc, ncol0;
    if (is_qv) {
        ah = Ah; al = Al;
        bh = Wqh + (size_t)ntile * 128 * DIM;
        C = Cqv; ldc = 2 * DIM; ncol0 = ntile * 128;
    } else {
        ah = Ph; al = Pl;
        bh = Wkh + (size_t)(ntile - 32) * 128 * DIM;
        C = Ck1; ldc = DIM; ncol0 = (ntile - 32) * 128;
    }

    // loader role: row r, byte-half q (0 or 32) of the 64B chunk row
    int r = tid >> 1, q = (tid & 1) * 32;
    const char* sAh = (const char*)(ah + (size_t)(mtile * 128 + r) * DIM) + q;
    const char* sAl = (const char*)(al + (size_t)(mtile * 128 + r) * DIM) + q;
    const char* sBh = (const char*)(bh + (size_t)r * DIM) + q;
    uint32_t dbase = sb + r * PITCH + q;

    // compute role
    int warp_m = wid >> 2, warp_n = wid & 3;
    int g = lane >> 2, tig = lane & 3;
    float acc[4][4][4] = {};
    uint32_t fA_h = sb + (warp_m * 64 + g) * PITCH + tig * 4;
    uint32_t fA_l = fA_h + TILEB;
    uint32_t fB_h = sb + 2 * TILEB + (warp_n * 32 + g) * PITCH + tig * 4;

    // prologue: fill 4 stages
    #pragma unroll
    for (int s = 0; s < NSTAGE; s++) {
        uint32_t d = dbase + s * STAGEB;
        cpa16(d,             sAh + s * 64); cpa16(d + 16,             sAh + s * 64 + 16);
        cpa16(d + TILEB,     sAl + s * 64); cpa16(d + TILEB + 16,     sAl + s * 64 + 16);
        cpa16(d + 2 * TILEB, sBh + s * 64); cpa16(d + 2 * TILEB + 16, sBh + s * 64 + 16);
        CP_COMMIT();
    }

    for (int c = 0; c < CHUNKS; ++c) {
        int s = c & (NSTAGE - 1);
        uint32_t so = (uint32_t)s * STAGEB;
        CP_WAIT3();
        __syncthreads();

        #pragma unroll
        for (int ks = 0; ks < 2; ks++) {
            uint32_t kb = so + ks * 32;
            uint32_t Ahf[4][4], Alf[4][4], Bf[4][2];
            #pragma unroll
            for (int i = 0; i < 4; i++) {
                uint32_t ph = fA_h + i * 16 * PITCH + kb;
                uint32_t pl = fA_l + i * 16 * PITCH + kb;
                asm volatile("ld.shared.b32 %0, [%1];" : "=r"(Ahf[i][0]) : "r"(ph));
                asm volatile("ld.shared.b32 %0, [%1];" : "=r"(Ahf[i][1]) : "r"(ph + 8 * PITCH));
                asm volatile("ld.shared.b32 %0, [%1];" : "=r"(Ahf[i][2]) : "r"(ph + 16));
                asm volatile("ld.shared.b32 %0, [%1];" : "=r"(Ahf[i][3]) : "r"(ph + 8 * PITCH + 16));
                asm volatile("ld.shared.b32 %0, [%1];" : "=r"(Alf[i][0]) : "r"(pl));
                asm volatile("ld.shared.b32 %0, [%1];" : "=r"(Alf[i][1]) : "r"(pl + 8 * PITCH));
                asm volatile("ld.shared.b32 %0, [%1];" : "=r"(Alf[i][2]) : "r"(pl + 16));
                asm volatile("ld.shared.b32 %0, [%1];" : "=r"(Alf[i][3]) : "r"(pl + 8 * PITCH + 16));
            }
            #pragma unroll
            for (int j = 0; j < 4; j++) {
                uint32_t ph = fB_h + j * 8 * PITCH + kb;
                asm volatile("ld.shared.b32 %0, [%1];" : "=r"(Bf[j][0]) : "r"(ph));
                asm volatile("ld.shared.b32 %0, [%1];" : "=r"(Bf[j][1]) : "r"(ph + 16));
            }
            #pragma unroll
            for (int i = 0; i < 4; i++)
                #pragma unroll
                for (int j = 0; j < 4; j++) {
                    mma16816f(acc[i][j], Ahf[i], Bf[j]);
                    mma16816f(acc[i][j], Alf[i], Bf[j]);
                }
        }
        __syncthreads();

        int cn = c + NSTAGE;
        if (cn < CHUNKS) {
            uint32_t d = dbase + so;
            cpa16(d,             sAh + cn * 64); cpa16(d + 16,             sAh + cn * 64 + 16);
            cpa16(d + TILEB,     sAl + cn * 64); cpa16(d + TILEB + 16,     sAl + cn * 64 + 16);
            cpa16(d + 2 * TILEB, sBh + cn * 64); cpa16(d + 2 * TILEB + 16, sBh + cn * 64 + 16);
        }
        CP_COMMIT();
    }

    // epilogue
    #pragma unroll
    for (int i = 0; i < 4; i++) {
        int r0 = mtile * 128 + warp_m * 64 + i * 16 + g;
        #pragma unroll
        for (int j = 0; j < 4; j++) {
            int col = ncol0 + warp_n * 32 + j * 8 + 2 * tig;
            *(float2*)&C[(size_t)r0 * ldc + col]       = make_float2(acc[i][j][0], acc[i][j][1]);
            *(float2*)&C[(size_t)(r0 + 8) * ldc + col] = make_float2(acc[i][j][2], acc[i][j][3]);
        }
    }
}

// ---------------- 4) per-head LN of q (from qv) and k1 ---------------------
__global__ void ln_heads(const float* __restrict__ qv, const float* __restrict__ k1,
                         const float* __restrict__ lw, const float* __restrict__ lb,
                         float* __restrict__ qn, float* __restrict__ k1n) {
    int gw   = (blockIdx.x * blockDim.x + threadIdx.x) >> 5;
    int lane = threadIdx.x & 31;
    if (gw >= 2 * B_SZ * NH) return;
    int r = gw & (B_SZ * NH - 1);
    int b = r >> 3, h = r & 7;
    const float* src;
    float* dst;
    if (gw < B_SZ * NH) { src = qv + (size_t)b * 2 * DIM + h * HD; dst = qn  + (size_t)b * DIM + h * HD; }
    else                { src = k1 + (size_t)b * DIM     + h * HD; dst = k1n + (size_t)b * DIM + h * HD; }

    float x[8], s = 0.f, ss = 0.f;
    #pragma unroll
    for (int j = 0; j < 8; j++) {
        x[j] = src[lane + 32 * j];
        s += x[j]; ss += x[j] * x[j];
    }
    s = warp_sum(s); ss = warp_sum(ss);
    float mu = s * (1.0f / HD);
    float inv = rsqrtf(ss * (1.0f / HD) - mu * mu + EPS);
    #pragma unroll
    for (int j = 0; j < 8; j++) {
        int i = lane + 32 * j;
        dst[i] = (x[j] - mu) * inv * lw[i] + lb[i];
    }
}

// ---------------- 5) fused: 2x attention + 2x conv1d + LNs + GELUs ---------
__global__ void __launch_bounds__(256, 4)
fused_attn(const float* __restrict__ qn, const float* __restrict__ k1n,
           const float* __restrict__ k2n, const float* __restrict__ qv,
           const float* __restrict__ lw, const float* __restrict__ lb,
           const float* __restrict__ l2w, const float* __restrict__ l2b,
           const float* __restrict__ w1, const float* __restrict__ w2,
           float* __restrict__ out) {
    __shared__ float sQ[DIM], sK1[DIM], sK2[DIM], sV[DIM], sO1[DIM];
    __shared__ float cw1[192], cw2[192];
    __shared__ float rs[8], rss[8];
    float* sO2 = sK1;

    int b = blockIdx.x, t = threadIdx.x;
    int wid = t >> 5, lane = t & 31;

    for (int i = t; i < DIM; i += 256) {
        sQ[i]  = qn[(size_t)b * DIM + i];
        sK1[i] = k1n[(size_t)b * DIM + i];
        sK2[i] = k2n[(size_t)b * DIM + i];
        sV[i]  = qv[(size_t)b * 2 * DIM + DIM + i];
    }
    if (t < 192) { cw1[t] = w1[t]; cw2[t] = w2[t]; }
    __syncthreads();

    {
        float a[8];
        #pragma unroll
        for (int s = 0; s < 8; s++) {
            float p = 0.f;
            #pragma unroll
            for (int j = 0; j < 8; j++)
                p = fmaf(sQ[wid * HD + lane + 32 * j], sK1[s * HD + lane + 32 * j], p);
            a[s] = warp_sum(p) * (1.0f / 16.0f);
        }
        float m = a[0];
        #pragma unroll
        for (int s = 1; s < 8; s++) m = fmaxf(m, a[s]);
        float sum = 0.f;
        #pragma unroll
        for (int s = 0; s < 8; s++) { a[s] = expf(a[s] - m); sum += a[s]; }
        float inv = 1.0f / sum;
        #pragma unroll
        for (int j = 0; j < 8; j++) {
            int cc = lane + 32 * j;
            float acc = 0.f;
            #pragma unroll
            for (int s = 0; s < 8; s++) acc = fmaf(a[s], sV[s * HD + cc], acc);
            sO1[wid * HD + cc] = acc * inv;
        }
    }
    __syncthreads();

    {
        float a[8];
        #pragma unroll
        for (int s = 0; s < 8; s++) {
            float p = 0.f;
            #pragma unroll
            for (int j = 0; j < 8; j++)
                p = fmaf(sQ[wid * HD + lane + 32 * j], sK2[s * HD + lane + 32 * j], p);
            a[s] = warp_sum(p) * (1.0f / 16.0f);
        }
        float m = a[0];
        #pragma unroll
        for (int s = 1; s < 8; s++) m = fmaxf(m, a[s]);
        float sum = 0.f;
        #pragma unroll
        for (int s = 0; s < 8; s++) { a[s] = expf(a[s] - m); sum += a[s]; }
        float inv = 1.0f / sum;
        #pragma unroll
        for (int j = 0; j < 8; j++) {
            int cc = lane + 32 * j;
            float acc = 0.f;
            #pragma unroll
            for (int s = 0; s < 8; s++) acc = fmaf(a[s], sV[s * HD + cc], acc);
            sO2[wid * HD + cc] = acc * inv;
        }
    }
    __syncthreads();

    float c1[8], c2[8], g[8];
    #pragma unroll
    for (int j = 0; j < 8; j++) {
        int l = lane + 32 * j;
        float a1 = 0.f, a2 = 0.f;
        #pragma unroll
        for (int i = 0; i < 8; i++) {
            float xm = (l > 0)   ? sO1[i * HD + l - 1] : 0.f;
            float x0 =             sO1[i * HD + l];
            float xp = (l < 255) ? sO1[i * HD + l + 1] : 0.f;
            a1 = fmaf(cw1[wid * 24 + i * 3 + 0], xm, a1);
            a1 = fmaf(cw1[wid * 24 + i * 3 + 1], x0, a1);
            a1 = fmaf(cw1[wid * 24 + i * 3 + 2], xp, a1);
            float ym = (l > 0)   ? sO2[i * HD + l - 1] : 0.f;
            float y0 =             sO2[i * HD + l];
            float yp = (l < 255) ? sO2[i * HD + l + 1] : 0.f;
            a2 = fmaf(cw2[wid * 24 + i * 3 + 0], ym, a2);
            a2 = fmaf(cw2[wid * 24 + i * 3 + 1], y0, a2);
            a2 = fmaf(cw2[wid * 24 + i * 3 + 2], yp, a2);
        }
        c1[j] = a1; c2[j] = a2;
    }

    {
        float s = 0.f, ss = 0.f;
        #pragma unroll
        for (int j = 0; j < 8; j++) { s += c1[j]; ss += c1[j] * c1[j]; }
        s = warp_sum(s); ss = warp_sum(ss);
        float mu = s * (1.0f / HD), inv = rsqrtf(ss * (1.0f / HD) - mu * mu + EPS);
        #pragma unroll
        for (int j = 0; j < 8; j++) { int i = lane + 32 * j; c1[j] = (c1[j] - mu) * inv * lw[i] + lb[i]; }
    }
    {
        float s = 0.f, ss = 0.f;
        #pragma unroll
        for (int j = 0; j < 8; j++) { s += c2[j]; ss += c2[j] * c2[j]; }
        s = warp_sum(s); ss = warp_sum(ss);
        float mu = s * (1.0f / HD), inv = rsqrtf(ss * (1.0f / HD) - mu * mu + EPS);
        #pragma unroll
        for (int j = 0; j < 8; j++) { int i = lane + 32 * j; c2[j] = (c2[j] - mu) * inv * lw[i] + lb[i]; }
    }
    {
        float x[8], s = 0.f, ss = 0.f;
        #pragma unroll
        for (int j = 0; j < 8; j++) {
            x[j] = c1[j] + c2[j] + sV[wid * HD + lane + 32 * j];
            s += x[j]; ss += x[j] * x[j];
        }
        s = warp_sum(s); ss = warp_sum(ss);
        float mu = s * (1.0f / HD), inv = rsqrtf(ss * (1.0f / HD) - mu * mu + EPS);
        #pragma unroll
        for (int j = 0; j < 8; j++) {
            int i = lane + 32 * j;
            g[j] = gelu_tanh((x[j] - mu) * inv * lw[i] + lb[i]);
        }
    }
    {
        float s = 0.f, ss = 0.f;
        #pragma unroll
        for (int j = 0; j < 8; j++) { s += g[j]; ss += g[j] * g[j]; }
        s = warp_sum(s); ss = warp_sum(ss);
        if (lane == 0) { rs[wid] = s; rss[wid] = ss; }
        __syncthreads();
        float ts = 0.f, tss = 0.f;
        #pragma unroll
        for (int i = 0; i < 8; i++) { ts += rs[i]; tss += rss[i]; }
        float mu = ts * (1.0f / DIM), inv = rsqrtf(tss * (1.0f / DIM) - mu * mu + EPS);
        #pragma unroll
        for (int j = 0; j < 8; j++) {
            int idx = wid * HD + lane + 32 * j;
            float y = (g[j] - mu) * inv * l2w[idx] + l2b[idx];
            out[(size_t)b * DIM + idx] = gelu_tanh(y);
        }
    }
}

// ---------------- launch ----------------
extern "C" void kernel_launch(void* const* d_in, const int* in_sizes, int n_in,
                              void* d_out, int out_size) {
    const float* f_ad    = (const float*)d_in[0];
    const float* f_age   = (const float*)d_in[1];
    const float* mem     = (const float*)d_in[2];
    const float* age_gap = (const float*)d_in[3];
    const float* qv_W    = (const float*)d_in[4];
    const float* k1_W    = (const float*)d_in[5];
    // d_in[6] = k2_W : dead in the reference — skipped
    const float* ln_w    = (const float*)d_in[7];
    const float* ln_b    = (const float*)d_in[8];
    const float* ln2_w   = (const float*)d_in[9];
    const float* ln2_b   = (const float*)d_in[10];
    const float* agf_rW  = (const float*)d_in[11];
    const float* agf_rb  = (const float*)d_in[12];
    const float* agf_eW  = (const float*)d_in[13];
    const float* agf_eb  = (const float*)d_in[14];
    const float* c1W     = (const float*)d_in[15];
    const float* c2W     = (const float*)d_in[16];
    float* out = (float*)d_out;

    float *qvb, *k1b, *qn, *k1n, *k2n;
    __half *Wqh, *Wkh, *Ahp, *Alp, *Php, *Plp;
    cudaGetSymbolAddress((void**)&qvb, g_qv);
    cudaGetSymbolAddress((void**)&k1b, g_k1);
    cudaGetSymbolAddress((void**)&qn, g_qn);
    cudaGetSymbolAddress((void**)&k1n, g_k1n);
    cudaGetSymbolAddress((void**)&k2n, g_k2n);
    cudaGetSymbolAddress((void**)&Wqh, g_Wqvh);
    cudaGetSymbolAddress((void**)&Wkh, g_Wk1h);
    cudaGetSymbolAddress((void**)&Ahp, g_Ah);
    cudaGetSymbolAddress((void**)&Alp, g_Al);
    cudaGetSymbolAddress((void**)&Php, g_Ph);
    cudaGetSymbolAddress((void**)&Plp, g_Pl);

    cudaFuncSetAttribute(gemm_tc, cudaFuncAttributeMaxDynamicSharedMemorySize, GEMM_SMEM);

    // pool mem -> pooled (hi, lo) fp16
    pool_kernel<<<(B_SZ * DIM * 32) / 256, 256>>>(mem, Php, Plp);
    // weights -> fp16 hi; f_ad -> fp16 exact split
    convert_hi<<<(2 * DIM * DIM / 4 + 255) / 256, 256>>>(
        (const float4*)qv_W, (uint2*)Wqh, 2 * DIM * DIM / 4);
    convert_hi<<<(DIM * DIM / 4 + 255) / 256, 256>>>(
        (const float4*)k1_W, (uint2*)Wkh, DIM * DIM / 4);
    convert_split<<<(B_SZ * DIM / 4 + 255) / 256, 256>>>(
        (const float4*)f_ad, (uint2*)Ahp, (uint2*)Alp, B_SZ * DIM / 4);
    // AGF branch
    agf_kernel<<<B_SZ, 256>>>(f_age, age_gap, agf_rW, agf_rb, agf_eW, agf_eb, ln_w, ln_b, k2n);
    // tensor-core GEMMs (fp16 2-term)
    gemm_tc<<<dim3(48, 2), 256, GEMM_SMEM>>>(Ahp, Alp, Php, Plp, Wqh, Wkh, qvb, k1b);
    // per-head LN
    ln_heads<<<(2 * B_SZ * NH) / 8, 256>>>(qvb, k1b, ln_w, ln_b, qn, k1n);
    // fused attention + conv + epilogue
    fused_attn<<<B_SZ, 256>>>(qn, k1n, k2n, qvb, ln_w, ln_b, ln2_w, ln2_b, c1W, c2W, out);
}

// round 6
// speedup vs baseline: 3.0012x; 1.2641x over previous
#include <cuda_runtime.h>
#include <cuda_fp16.h>
#include <math.h>
#include <stdint.h>

#define B_SZ 256
#define DIM 2048
#define NH 8
#define HD 256
#define EPS 1e-5f

// ---------------- scratch (device globals; no allocation allowed) ----------
__device__ float g_qv[B_SZ * 2 * DIM];
__device__ float g_k1[B_SZ * DIM];
__device__ float g_k2n[B_SZ * DIM];
__device__ __half g_Wqvh[2 * DIM * DIM];
__device__ __half g_Wk1h[DIM * DIM];
__device__ __half g_Ah[B_SZ * DIM];      // f_ad fp16
__device__ __half g_Ph[B_SZ * DIM];      // pooled fp16

// ---------------- helpers ----------------
__device__ __forceinline__ float warp_sum(float v) {
    v += __shfl_xor_sync(0xffffffffu, v, 16);
    v += __shfl_xor_sync(0xffffffffu, v, 8);
    v += __shfl_xor_sync(0xffffffffu, v, 4);
    v += __shfl_xor_sync(0xffffffffu, v, 2);
    v += __shfl_xor_sync(0xffffffffu, v, 1);
    return v;
}

__device__ __forceinline__ float gelu_tanh(float x) {
    const float k = 0.7978845608028654f;
    float x3 = x * x * x;
    return 0.5f * x * (1.0f + tanhf(k * (x + 0.044715f * x3)));
}

__device__ __forceinline__ uint32_t smem_u32(const void* p) {
    uint32_t a;
    asm("{ .reg .u64 t; cvta.to.shared.u64 t, %1; cvt.u32.u64 %0, t; }" : "=r"(a) : "l"(p));
    return a;
}

__device__ __forceinline__ void cpa16(uint32_t dst, const void* src) {
    asm volatile("cp.async.cg.shared.global [%0], [%1], 16;" :: "r"(dst), "l"(src));
}
#define CP_COMMIT() asm volatile("cp.async.commit_group;" ::: "memory")
#define CP_WAIT3()  asm volatile("cp.async.wait_group 3;" ::: "memory")

// fp16 mma: D(16x8,f32) += A(16x16,f16) * B(16x8,f16)
__device__ __forceinline__ void mma16816f(float* d, const uint32_t* a, const uint32_t* b) {
    asm volatile(
        "mma.sync.aligned.m16n8k16.row.col.f32.f16.f16.f32 "
        "{%0,%1,%2,%3}, {%4,%5,%6,%7}, {%8,%9}, {%0,%1,%2,%3};"
        : "+f"(d[0]), "+f"(d[1]), "+f"(d[2]), "+f"(d[3])
        : "r"(a[0]), "r"(a[1]), "r"(a[2]), "r"(a[3]), "r"(b[0]), "r"(b[1]));
}

// ---------------- 1) prep über-kernel: pool + converts + AGF ---------------
// block ranges: [0,65536) pool | [..,+8192) qv_W | [+4096) k1_W | [+512) f_ad | [+256) agf
#define NB_POOL 65536
#define NB_WQV  8192
#define NB_WK1  4096
#define NB_FAD  512
#define NB_AGF  256
#define NB_PREP (NB_POOL + NB_WQV + NB_WK1 + NB_FAD + NB_AGF)

__global__ void prep_kernel(const float* __restrict__ mem,
                            const float4* __restrict__ qv_W, const float4* __restrict__ k1_W,
                            const float4* __restrict__ f_ad,
                            const float* __restrict__ f_age, const float* __restrict__ age_gap,
                            const float* __restrict__ rW, const float* __restrict__ rb,
                            const float* __restrict__ eW, const float* __restrict__ eb,
                            const float* __restrict__ lw, const float* __restrict__ lb,
                            __half* __restrict__ Ph, __half* __restrict__ Wqh,
                            __half* __restrict__ Wkh, __half* __restrict__ Ah,
                            float* __restrict__ k2n) {
    __shared__ float srow[DIM];
    __shared__ float pr[8];
    int bx = blockIdx.x;
    int t = threadIdx.x, wid = t >> 5, lane = t & 31;

    if (bx < NB_POOL) {
        // mean-pool mem over 64 spatial elems; one warp per output
        int gw = bx * 8 + wid;
        const float2 v = *(const float2*)&mem[(size_t)gw * 64 + lane * 2];
        float s = warp_sum(v.x + v.y);
        if (lane == 0) Ph[gw] = __float2half_rn(s * (1.0f / 64.0f));
        return;
    }
    bx -= NB_POOL;
    if (bx < NB_WQV + NB_WK1 + NB_FAD) {
        const float4* src;
        uint2* dst;
        int i;
        if (bx < NB_WQV)               { src = qv_W; dst = (uint2*)Wqh; i = bx * 256 + t; }
        else if (bx < NB_WQV + NB_WK1) { src = k1_W; dst = (uint2*)Wkh; i = (bx - NB_WQV) * 256 + t; }
        else                           { src = f_ad; dst = (uint2*)Ah;  i = (bx - NB_WQV - NB_WK1) * 256 + t; }
        float4 v = src[i];
        __half h0 = __float2half_rn(v.x), h1 = __float2half_rn(v.y);
        __half h2 = __float2half_rn(v.z), h3 = __float2half_rn(v.w);
        uint2 hp;
        hp.x = (uint32_t)__half_as_ushort(h0) | ((uint32_t)__half_as_ushort(h1) << 16);
        hp.y = (uint32_t)__half_as_ushort(h2) | ((uint32_t)__half_as_ushort(h3) << 16);
        dst[i] = hp;
        return;
    }
    // AGF branch + per-head LN -> k2_norm; one block per batch row
    int b = bx - (NB_WQV + NB_WK1 + NB_FAD);

    float part = 0.f;
    for (int i = t; i < DIM; i += 256) part += f_age[(size_t)b * DIM + i] * rW[i];
    part = warp_sum(part);
    if (lane == 0) pr[wid] = part;
    __syncthreads();
    float red = rb[0];
    #pragma unroll
    for (int i = 0; i < 8; i++) red += pr[i];
    float ag = age_gap[b];

    for (int i = t; i < DIM; i += 256) {
        srow[i] = f_age[(size_t)b * DIM + i] + eW[i * 2 + 0] * red + eW[i * 2 + 1] * ag + eb[i];
    }
    __syncthreads();

    float x[8], s = 0.f, ss = 0.f;
    #pragma unroll
    for (int j = 0; j < 8; j++) {
        x[j] = srow[wid * HD + lane + 32 * j];
        s += x[j]; ss += x[j] * x[j];
    }
    s = warp_sum(s); ss = warp_sum(ss);
    float mu = s * (1.0f / HD);
    float inv = rsqrtf(ss * (1.0f / HD) - mu * mu + EPS);
    #pragma unroll
    for (int j = 0; j < 8; j++) {
        int i = lane + 32 * j;
        k2n[(size_t)b * DIM + wid * HD + i] = (x[j] - mu) * inv * lw[i] + lb[i];
    }
}

// ---------------- 2) tensor-core GEMM, fp16 1-term, cp.async 4-stage -------
// C[m,n] = sum_k A[m,k]*W[n,k]  with A,W rounded to fp16 (fp32 accum)
// CTA tile M=128 N=128; K chunks of 64 (4 k-steps). 8 warps 2x4, warp 64x32.
#define CHUNKS 32
#define PITCH 144                       // 128B data + 16B pad; frag banks (4g+tig)%32 unique
#define TILEB (128 * PITCH)             // 18432
#define NSTAGE 4
#define STAGEB (2 * TILEB)              // A, B
#define GEMM_SMEM (NSTAGE * STAGEB)     // 147456

__global__ void __launch_bounds__(256, 1)
gemm_tc(const __half* __restrict__ Ah, const __half* __restrict__ Ph,
        const __half* __restrict__ Wqh, const __half* __restrict__ Wkh,
        float* __restrict__ Cqv, float* __restrict__ Ck1) {
    extern __shared__ char sm[];
    uint32_t sb = smem_u32(sm);
    int tid = threadIdx.x, wid = tid >> 5, lane = tid & 31;
    int ntile = blockIdx.x, mtile = blockIdx.y;

    bool is_qv = ntile < 32;
    const __half *a, *bw;
    float* C;
    int ldc, ncol0;
    if (is_qv) {
        a = Ah; bw = Wqh + (size_t)ntile * 128 * DIM;
        C = Cqv; ldc = 2 * DIM; ncol0 = ntile * 128;
    } else {
        a = Ph; bw = Wkh + (size_t)(ntile - 32) * 128 * DIM;
        C = Ck1; ldc = DIM; ncol0 = (ntile - 32) * 128;
    }

    // loader role: row r, byte-half q (0 or 64) of the 128B chunk row
    int r = tid >> 1, q = (tid & 1) * 64;
    const char* sA = (const char*)(a + (size_t)(mtile * 128 + r) * DIM) + q;
    const char* sB = (const char*)(bw + (size_t)r * DIM) + q;
    uint32_t da = sb + r * PITCH + q;
    uint32_t db = da + TILEB;

    // compute role
    int warp_m = wid >> 2, warp_n = wid & 3;
    int g = lane >> 2, tig = lane & 3;
    float acc[4][4][4] = {};
    uint32_t fA = sb + (warp_m * 64 + g) * PITCH + tig * 4;
    uint32_t fB = sb + TILEB + (warp_n * 32 + g) * PITCH + tig * 4;

    // prologue: fill 4 stages (chunk row = 128 bytes)
    #pragma unroll
    for (int s = 0; s < NSTAGE; s++) {
        uint32_t o = s * STAGEB;
        const char* pa = sA + s * 128;
        const char* pb = sB + s * 128;
        cpa16(da + o, pa);      cpa16(da + o + 16, pa + 16);
        cpa16(da + o + 32, pa + 32); cpa16(da + o + 48, pa + 48);
        cpa16(db + o, pb);      cpa16(db + o + 16, pb + 16);
        cpa16(db + o + 32, pb + 32); cpa16(db + o + 48, pb + 48);
        CP_COMMIT();
    }

    for (int c = 0; c < CHUNKS; ++c) {
        uint32_t so = (uint32_t)(c & (NSTAGE - 1)) * STAGEB;
        CP_WAIT3();
        __syncthreads();

        #pragma unroll
        for (int ks = 0; ks < 4; ks++) {
            uint32_t kb = so + ks * 32;
            uint32_t Af[4][4], Bf[4][2];
            #pragma unroll
            for (int i = 0; i < 4; i++) {
                uint32_t ph = fA + i * 16 * PITCH + kb;
                asm volatile("ld.shared.b32 %0, [%1];" : "=r"(Af[i][0]) : "r"(ph));
                asm volatile("ld.shared.b32 %0, [%1];" : "=r"(Af[i][1]) : "r"(ph + 8 * PITCH));
                asm volatile("ld.shared.b32 %0, [%1];" : "=r"(Af[i][2]) : "r"(ph + 16));
                asm volatile("ld.shared.b32 %0, [%1];" : "=r"(Af[i][3]) : "r"(ph + 8 * PITCH + 16));
            }
            #pragma unroll
            for (int j = 0; j < 4; j++) {
                uint32_t ph = fB + j * 8 * PITCH + kb;
                asm volatile("ld.shared.b32 %0, [%1];" : "=r"(Bf[j][0]) : "r"(ph));
                asm volatile("ld.shared.b32 %0, [%1];" : "=r"(Bf[j][1]) : "r"(ph + 16));
            }
            #pragma unroll
            for (int i = 0; i < 4; i++)
                #pragma unroll
                for (int j = 0; j < 4; j++)
                    mma16816f(acc[i][j], Af[i], Bf[j]);
        }
        __syncthreads();

        int cn = c + NSTAGE;
        if (cn < CHUNKS) {
            const char* pa = sA + cn * 128;
            const char* pb = sB + cn * 128;
            cpa16(da + so, pa);      cpa16(da + so + 16, pa + 16);
            cpa16(da + so + 32, pa + 32); cpa16(da + so + 48, pa + 48);
            cpa16(db + so, pb);      cpa16(db + so + 16, pb + 16);
            cpa16(db + so + 32, pb + 32); cpa16(db + so + 48, pb + 48);
        }
        CP_COMMIT();
    }

    // epilogue
    #pragma unroll
    for (int i = 0; i < 4; i++) {
        int r0 = mtile * 128 + warp_m * 64 + i * 16 + g;
        #pragma unroll
        for (int j = 0; j < 4; j++) {
            int col = ncol0 + warp_n * 32 + j * 8 + 2 * tig;
            *(float2*)&C[(size_t)r0 * ldc + col]       = make_float2(acc[i][j][0], acc[i][j][1]);
            *(float2*)&C[(size_t)(r0 + 8) * ldc + col] = make_float2(acc[i][j][2], acc[i][j][3]);
        }
    }
}

// ---------------- 3) fused: head-LN(q,k1) + 2x attn + 2x conv1d + LNs + GELUs
__global__ void __launch_bounds__(256, 4)
fused_attn(const float* __restrict__ qv, const float* __restrict__ k1,
           const float* __restrict__ k2n,
           const float* __restrict__ lw, const float* __restrict__ lb,
           const float* __restrict__ l2w, const float* __restrict__ l2b,
           const float* __restrict__ w1, const float* __restrict__ w2,
           float* __restrict__ out) {
    __shared__ float sQ[DIM], sK1[DIM], sK2[DIM], sV[DIM], sO1[DIM];
    __shared__ float cw1[192], cw2[192];
    __shared__ float rs[8], rss[8];
    float* sO2 = sK1;

    int b = blockIdx.x, t = threadIdx.x;
    int wid = t >> 5, lane = t & 31;

    // per-head LN of q (from qv) and k1, each warp = one head
    {
        float x[8], s = 0.f, ss = 0.f;
        #pragma unroll
        for (int j = 0; j < 8; j++) {
            x[j] = qv[(size_t)b * 2 * DIM + wid * HD + lane + 32 * j];
            s += x[j]; ss += x[j] * x[j];
        }
        s = warp_sum(s); ss = warp_sum(ss);
        float mu = s * (1.0f / HD), inv = rsqrtf(ss * (1.0f / HD) - mu * mu + EPS);
        #pragma unroll
        for (int j = 0; j < 8; j++) {
            int i = lane + 32 * j;
            sQ[wid * HD + i] = (x[j] - mu) * inv * lw[i] + lb[i];
        }
    }
    {
        float x[8], s = 0.f, ss = 0.f;
        #pragma unroll
        for (int j = 0; j < 8; j++) {
            x[j] = k1[(size_t)b * DIM + wid * HD + lane + 32 * j];
            s += x[j]; ss += x[j] * x[j];
        }
        s = warp_sum(s); ss = warp_sum(ss);
        float mu = s * (1.0f / HD), inv = rsqrtf(ss * (1.0f / HD) - mu * mu + EPS);
        #pragma unroll
        for (int j = 0; j < 8; j++) {
            int i = lane + 32 * j;
            sK1[wid * HD + i] = (x[j] - mu) * inv * lw[i] + lb[i];
        }
    }
    for (int i = t; i < DIM; i += 256) {
        sK2[i] = k2n[(size_t)b * DIM + i];
        sV[i]  = qv[(size_t)b * 2 * DIM + DIM + i];
    }
    if (t < 192) { cw1[t] = w1[t]; cw2[t] = w2[t]; }
    __syncthreads();

    // ---- attention 1 (sQ vs sK1, value sV) -> sO1 ----
    {
        float a[8];
        #pragma unroll
        for (int s = 0; s < 8; s++) {
            float p = 0.f;
            #pragma unroll
            for (int j = 0; j < 8; j++)
                p = fmaf(sQ[wid * HD + lane + 32 * j], sK1[s * HD + lane + 32 * j], p);
            a[s] = warp_sum(p) * (1.0f / 16.0f);
        }
        float m = a[0];
        #pragma unroll
        for (int s = 1; s < 8; s++) m = fmaxf(m, a[s]);
        float sum = 0.f;
        #pragma unroll
        for (int s = 0; s < 8; s++) { a[s] = expf(a[s] - m); sum += a[s]; }
        float inv = 1.0f / sum;
        #pragma unroll
        for (int j = 0; j < 8; j++) {
            int cc = lane + 32 * j;
            float acc = 0.f;
            #pragma unroll
            for (int s = 0; s < 8; s++) acc = fmaf(a[s], sV[s * HD + cc], acc);
            sO1[wid * HD + cc] = acc * inv;
        }
    }
    __syncthreads();

    // ---- attention 2 (sQ vs sK2) -> sO2 (aliases sK1) ----
    {
        float a[8];
        #pragma unroll
        for (int s = 0; s < 8; s++) {
            float p = 0.f;
            #pragma unroll
            for (int j = 0; j < 8; j++)
                p = fmaf(sQ[wid * HD + lane + 32 * j], sK2[s * HD + lane + 32 * j], p);
            a[s] = warp_sum(p) * (1.0f / 16.0f);
        }
        float m = a[0];
        #pragma unroll
        for (int s = 1; s < 8; s++) m = fmaxf(m, a[s]);
        float sum = 0.f;
        #pragma unroll
        for (int s = 0; s < 8; s++) { a[s] = expf(a[s] - m); sum += a[s]; }
        float inv = 1.0f / sum;
        #pragma unroll
        for (int j = 0; j < 8; j++) {
            int cc = lane + 32 * j;
            float acc = 0.f;
            #pragma unroll
            for (int s = 0; s < 8; s++) acc = fmaf(a[s], sV[s * HD + cc], acc);
            sO2[wid * HD + cc] = acc * inv;
        }
    }
    __syncthreads();

    // ---- conv1d (C=8, K=3, pad 1) + LNs + sum + LN + gelu + LN2 + gelu ----
    float c1[8], c2[8], g[8];
    #pragma unroll
    for (int j = 0; j < 8; j++) {
        int l = lane + 32 * j;
        float a1 = 0.f, a2 = 0.f;
        #pragma unroll
        for (int i = 0; i < 8; i++) {
            float xm = (l > 0)   ? sO1[i * HD + l - 1] : 0.f;
            float x0 =             sO1[i * HD + l];
            float xp = (l < 255) ? sO1[i * HD + l + 1] : 0.f;
            a1 = fmaf(cw1[wid * 24 + i * 3 + 0], xm, a1);
            a1 = fmaf(cw1[wid * 24 + i * 3 + 1], x0, a1);
            a1 = fmaf(cw1[wid * 24 + i * 3 + 2], xp, a1);
            float ym = (l > 0)   ? sO2[i * HD + l - 1] : 0.f;
            float y0 =             sO2[i * HD + l];
            float yp = (l < 255) ? sO2[i * HD + l + 1] : 0.f;
            a2 = fmaf(cw2[wid * 24 + i * 3 + 0], ym, a2);
            a2 = fmaf(cw2[wid * 24 + i * 3 + 1], y0, a2);
            a2 = fmaf(cw2[wid * 24 + i * 3 + 2], yp, a2);
        }
        c1[j] = a1; c2[j] = a2;
    }

    {
        float s = 0.f, ss = 0.f;
        #pragma unroll
        for (int j = 0; j < 8; j++) { s += c1[j]; ss += c1[j] * c1[j]; }
        s = warp_sum(s); ss = warp_sum(ss);
        float mu = s * (1.0f / HD), inv = rsqrtf(ss * (1.0f / HD) - mu * mu + EPS);
        #pragma unroll
        for (int j = 0; j < 8; j++) { int i = lane + 32 * j; c1[j] = (c1[j] - mu) * inv * lw[i] + lb[i]; }
    }
    {
        float s = 0.f, ss = 0.f;
        #pragma unroll
        for (int j = 0; j < 8; j++) { s += c2[j]; ss += c2[j] * c2[j]; }
        s = warp_sum(s); ss = warp_sum(ss);
        float mu = s * (1.0f / HD), inv = rsqrtf(ss * (1.0f / HD) - mu * mu + EPS);
        #pragma unroll
        for (int j = 0; j < 8; j++) { int i = lane + 32 * j; c2[j] = (c2[j] - mu) * inv * lw[i] + lb[i]; }
    }
    {
        float x[8], s = 0.f, ss = 0.f;
        #pragma unroll
        for (int j = 0; j < 8; j++) {
            x[j] = c1[j] + c2[j] + sV[wid * HD + lane + 32 * j];
            s += x[j]; ss += x[j] * x[j];
        }
        s = warp_sum(s); ss = warp_sum(ss);
        float mu = s * (1.0f / HD), inv = rsqrtf(ss * (1.0f / HD) - mu * mu + EPS);
        #pragma unroll
        for (int j = 0; j < 8; j++) {
            int i = lane + 32 * j;
            g[j] = gelu_tanh((x[j] - mu) * inv * lw[i] + lb[i]);
        }
    }
    {
        float s = 0.f, ss = 0.f;
        #pragma unroll
        for (int j = 0; j < 8; j++) { s += g[j]; ss += g[j] * g[j]; }
        s = warp_sum(s); ss = warp_sum(ss);
        if (lane == 0) { rs[wid] = s; rss[wid] = ss; }
        __syncthreads();
        float ts = 0.f, tss = 0.f;
        #pragma unroll
        for (int i = 0; i < 8; i++) { ts += rs[i]; tss += rss[i]; }
        float mu = ts * (1.0f / DIM), inv = rsqrtf(tss * (1.0f / DIM) - mu * mu + EPS);
        #pragma unroll
        for (int j = 0; j < 8; j++) {
            int idx = wid * HD + lane + 32 * j;
            float y = (g[j] - mu) * inv * l2w[idx] + l2b[idx];
            out[(size_t)b * DIM + idx] = gelu_tanh(y);
        }
    }
}

// ---------------- launch ----------------
extern "C" void kernel_launch(void* const* d_in, const int* in_sizes, int n_in,
                              void* d_out, int out_size) {
    const float* f_ad    = (const float*)d_in[0];
    const float* f_age   = (const float*)d_in[1];
    const float* mem     = (const float*)d_in[2];
    const float* age_gap = (const float*)d_in[3];
    const float* qv_W    = (const float*)d_in[4];
    const float* k1_W    = (const float*)d_in[5];
    // d_in[6] = k2_W : dead in the reference — skipped
    const float* ln_w    = (const float*)d_in[7];
    const float* ln_b    = (const float*)d_in[8];
    const float* ln2_w   = (const float*)d_in[9];
    const float* ln2_b   = (const float*)d_in[10];
    const float* agf_rW  = (const float*)d_in[11];
    const float* agf_rb  = (const float*)d_in[12];
    const float* agf_eW  = (const float*)d_in[13];
    const float* agf_eb  = (const float*)d_in[14];
    const float* c1W     = (const float*)d_in[15];
    const float* c2W     = (const float*)d_in[16];
    float* out = (float*)d_out;

    float *qvb, *k1b, *k2n;
    __half *Wqh, *Wkh, *Ahp, *Php;
    cudaGetSymbolAddress((void**)&qvb, g_qv);
    cudaGetSymbolAddress((void**)&k1b, g_k1);
    cudaGetSymbolAddress((void**)&k2n, g_k2n);
    cudaGetSymbolAddress((void**)&Wqh, g_Wqvh);
    cudaGetSymbolAddress((void**)&Wkh, g_Wk1h);
    cudaGetSymbolAddress((void**)&Ahp, g_Ah);
    cudaGetSymbolAddress((void**)&Php, g_Ph);

    cudaFuncSetAttribute(gemm_tc, cudaFuncAttributeMaxDynamicSharedMemorySize, GEMM_SMEM);

    // 1) prep: pool + fp16 converts + AGF (all independent work, one launch)
    prep_kernel<<<NB_PREP, 256>>>(mem, (const float4*)qv_W, (const float4*)k1_W,
                                  (const float4*)f_ad, f_age, age_gap,
                                  agf_rW, agf_rb, agf_eW, agf_eb, ln_w, ln_b,
                                  Php, Wqh, Wkh, Ahp, k2n);
    // 2) tensor-core GEMMs (fp16 1-term)
    gemm_tc<<<dim3(48, 2), 256, GEMM_SMEM>>>(Ahp, Php, Wqh, Wkh, qvb, k1b);
    // 3) fused head-LN + attention + conv + epilogue
    fused_attn<<<B_SZ, 256>>>(qvb, k1b, k2n, ln_w, ln_b, ln2_w, ln2_b, c1W, c2W, out);
}

// round 8
// speedup vs baseline: 3.7112x; 1.2366x over previous
#include <cuda_runtime.h>
#include <cuda_fp16.h>
#include <math.h>
#include <stdint.h>

#define B_SZ 256
#define DIM 2048
#define NH 8
#define HD 256
#define EPS 1e-5f

// ---------------- scratch (device globals; no allocation allowed) ----------
__device__ float g_qv[B_SZ * 2 * DIM];
__device__ float g_k1[B_SZ * DIM];
__device__ float g_k2n[B_SZ * DIM];
__device__ __half g_Wqvh[2 * DIM * DIM];
__device__ __half g_Wk1h[DIM * DIM];
__device__ __half g_Ah[B_SZ * DIM];      // f_ad fp16
__device__ __half g_Ph[B_SZ * DIM];      // pooled fp16

// ---------------- helpers ----------------
__device__ __forceinline__ float warp_sum(float v) {
    v += __shfl_xor_sync(0xffffffffu, v, 16);
    v += __shfl_xor_sync(0xffffffffu, v, 8);
    v += __shfl_xor_sync(0xffffffffu, v, 4);
    v += __shfl_xor_sync(0xffffffffu, v, 2);
    v += __shfl_xor_sync(0xffffffffu, v, 1);
    return v;
}

__device__ __forceinline__ float gelu_tanh(float x) {
    const float k = 0.7978845608028654f;
    float x3 = x * x * x;
    return 0.5f * x * (1.0f + tanhf(k * (x + 0.044715f * x3)));
}

__device__ __forceinline__ uint32_t smem_u32(const void* p) {
    uint32_t a;
    asm("{ .reg .u64 t; cvta.to.shared.u64 t, %1; cvt.u32.u64 %0, t; }" : "=r"(a) : "l"(p));
    return a;
}

__device__ __forceinline__ void cpa16(uint32_t dst, const void* src) {
    asm volatile("cp.async.cg.shared.global [%0], [%1], 16;" :: "r"(dst), "l"(src));
}
#define CP_COMMIT() asm volatile("cp.async.commit_group;" ::: "memory")
#define CP_WAIT3()  asm volatile("cp.async.wait_group 3;" ::: "memory")

// fp16 mma: D(16x8,f32) += A(16x16,f16) * B(16x8,f16)
__device__ __forceinline__ void mma16816f(float* d, const uint32_t* a, const uint32_t* b) {
    asm volatile(
        "mma.sync.aligned.m16n8k16.row.col.f32.f16.f16.f32 "
        "{%0,%1,%2,%3}, {%4,%5,%6,%7}, {%8,%9}, {%0,%1,%2,%3};"
        : "+f"(d[0]), "+f"(d[1]), "+f"(d[2]), "+f"(d[3])
        : "r"(a[0]), "r"(a[1]), "r"(a[2]), "r"(a[3]), "r"(b[0]), "r"(b[1]));
}

// ---------------- 1) prep über-kernel: pool + converts + AGF ---------------
// block ranges: pool | qv_W cvt | k1_W cvt | f_ad cvt | agf
#define NB_POOL 2048          // 256 threads/blk, 1 output each (16 LDG.128/thread)
#define NB_WQV  2048          // 1024 float4 per block (4/thread)
#define NB_WK1  1024
#define NB_FAD  128
#define NB_AGF  256
#define NB_PREP (NB_POOL + NB_WQV + NB_WK1 + NB_FAD + NB_AGF)

__global__ void prep_kernel(const float* __restrict__ mem,
                            const float4* __restrict__ qv_W, const float4* __restrict__ k1_W,
                            const float4* __restrict__ f_ad,
                            const float* __restrict__ f_age, const float* __restrict__ age_gap,
                            const float* __restrict__ rW, const float* __restrict__ rb,
                            const float* __restrict__ eW, const float* __restrict__ eb,
                            const float* __restrict__ lw, const float* __restrict__ lb,
                            __half* __restrict__ Ph, __half* __restrict__ Wqh,
                            __half* __restrict__ Wkh, __half* __restrict__ Ah,
                            float* __restrict__ k2n) {
    __shared__ float srow[DIM];
    __shared__ float pr[8];
    int bx = blockIdx.x;
    int t = threadIdx.x, wid = t >> 5, lane = t & 31;

    if (bx < NB_POOL) {
        // mean-pool: one output per thread; 16 independent LDG.128 (MLP=16)
        int gid = bx * 256 + t;                       // 0 .. 524287
        const float4* p = (const float4*)(mem + (size_t)gid * 64);
        float4 a = make_float4(0.f, 0.f, 0.f, 0.f);
        #pragma unroll
        for (int i = 0; i < 16; i++) {
            float4 v = p[i];
            a.x += v.x; a.y += v.y; a.z += v.z; a.w += v.w;
        }
        Ph[gid] = __float2half_rn((a.x + a.y + a.z + a.w) * (1.0f / 64.0f));
        return;
    }
    bx -= NB_POOL;
    if (bx < NB_WQV + NB_WK1 + NB_FAD) {
        // fp32 -> fp16 convert: 4 independent float4 per thread
        const float4* src;
        uint2* dst;
        int i0;
        if (bx < NB_WQV)               { src = qv_W; dst = (uint2*)Wqh; i0 = bx * 1024 + t; }
        else if (bx < NB_WQV + NB_WK1) { src = k1_W; dst = (uint2*)Wkh; i0 = (bx - NB_WQV) * 1024 + t; }
        else                           { src = f_ad; dst = (uint2*)Ah;  i0 = (bx - NB_WQV - NB_WK1) * 1024 + t; }
        #pragma unroll
        for (int k = 0; k < 4; k++) {
            int i = i0 + k * 256;
            float4 v = src[i];
            __half h0 = __float2half_rn(v.x), h1 = __float2half_rn(v.y);
            __half h2 = __float2half_rn(v.z), h3 = __float2half_rn(v.w);
            uint2 hp;
            hp.x = (uint32_t)__half_as_ushort(h0) | ((uint32_t)__half_as_ushort(h1) << 16);
            hp.y = (uint32_t)__half_as_ushort(h2) | ((uint32_t)__half_as_ushort(h3) << 16);
            dst[i] = hp;
        }
        return;
    }
    // AGF branch + per-head LN -> k2_norm; one block per batch row
    int b = bx - (NB_WQV + NB_WK1 + NB_FAD);

    float part = 0.f;
    for (int i = t; i < DIM; i += 256) part += f_age[(size_t)b * DIM + i] * rW[i];
    part = warp_sum(part);
    if (lane == 0) pr[wid] = part;
    __syncthreads();
    float red = rb[0];
    #pragma unroll
    for (int i = 0; i < 8; i++) red += pr[i];
    float ag = age_gap[b];

    for (int i = t; i < DIM; i += 256) {
        srow[i] = f_age[(size_t)b * DIM + i] + eW[i * 2 + 0] * red + eW[i * 2 + 1] * ag + eb[i];
    }
    __syncthreads();

    float x[8], s = 0.f, ss = 0.f;
    #pragma unroll
    for (int j = 0; j < 8; j++) {
        x[j] = srow[wid * HD + lane + 32 * j];
        s += x[j]; ss += x[j] * x[j];
    }
    s = warp_sum(s); ss = warp_sum(ss);
    float mu = s * (1.0f / HD);
    float inv = rsqrtf(ss * (1.0f / HD) - mu * mu + EPS);
    #pragma unroll
    for (int j = 0; j < 8; j++) {
        int i = lane + 32 * j;
        k2n[(size_t)b * DIM + wid * HD + i] = (x[j] - mu) * inv * lw[i] + lb[i];
    }
}

// ---------------- 2) tensor-core GEMM, fp16 1-term, cp.async 4-stage -------
// C[m,n] = sum_k A[m,k]*W[n,k]  with A,W rounded to fp16 (fp32 accum)
// CTA tile M=128 N=128; K chunks of 64 (4 k-steps). 8 warps 2x4, warp 64x32.
#define CHUNKS 32
#define PITCH 144                       // 128B data + 16B pad; frag banks (4g+tig)%32 unique
#define TILEB (128 * PITCH)             // 18432
#define NSTAGE 4
#define STAGEB (2 * TILEB)              // A, B
#define GEMM_SMEM (NSTAGE * STAGEB)     // 147456

__global__ void __launch_bounds__(256, 1)
gemm_tc(const __half* __restrict__ Ah, const __half* __restrict__ Ph,
        const __half* __restrict__ Wqh, const __half* __restrict__ Wkh,
        float* __restrict__ Cqv, float* __restrict__ Ck1) {
    extern __shared__ char sm[];
    uint32_t sb = smem_u32(sm);
    int tid = threadIdx.x, wid = tid >> 5, lane = tid & 31;
    int ntile = blockIdx.x, mtile = blockIdx.y;

    bool is_qv = ntile < 32;
    const __half *a, *bw;
    float* C;
    int ldc, ncol0;
    if (is_qv) {
        a = Ah; bw = Wqh + (size_t)ntile * 128 * DIM;
        C = Cqv; ldc = 2 * DIM; ncol0 = ntile * 128;
    } else {
        a = Ph; bw = Wkh + (size_t)(ntile - 32) * 128 * DIM;
        C = Ck1; ldc = DIM; ncol0 = (ntile - 32) * 128;
    }

    // loader role: row r, byte-half q (0 or 64) of the 128B chunk row
    int r = tid >> 1, q = (tid & 1) * 64;
    const char* sA = (const char*)(a + (size_t)(mtile * 128 + r) * DIM) + q;
    const char* sB = (const char*)(bw + (size_t)r * DIM) + q;
    uint32_t da = sb + r * PITCH + q;
    uint32_t db = da + TILEB;

    // compute role
    int warp_m = wid >> 2, warp_n = wid & 3;
    int g = lane >> 2, tig = lane & 3;
    float acc[4][4][4] = {};
    uint32_t fA = sb + (warp_m * 64 + g) * PITCH + tig * 4;
    uint32_t fB = sb + TILEB + (warp_n * 32 + g) * PITCH + tig * 4;

    // prologue: fill 4 stages (chunk row = 128 bytes)
    #pragma unroll
    for (int s = 0; s < NSTAGE; s++) {
        uint32_t o = s * STAGEB;
        const char* pa = sA + s * 128;
        const char* pb = sB + s * 128;
        cpa16(da + o, pa);      cpa16(da + o + 16, pa + 16);
        cpa16(da + o + 32, pa + 32); cpa16(da + o + 48, pa + 48);
        cpa16(db + o, pb);      cpa16(db + o + 16, pb + 16);
        cpa16(db + o + 32, pb + 32); cpa16(db + o + 48, pb + 48);
        CP_COMMIT();
    }

    for (int c = 0; c < CHUNKS; ++c) {
        uint32_t so = (uint32_t)(c & (NSTAGE - 1)) * STAGEB;
        CP_WAIT3();
        __syncthreads();

        #pragma unroll
        for (int ks = 0; ks < 4; ks++) {
            uint32_t kb = so + ks * 32;
            uint32_t Af[4][4], Bf[4][2];
            #pragma unroll
            for (int i = 0; i < 4; i++) {
                uint32_t ph = fA + i * 16 * PITCH + kb;
                asm volatile("ld.shared.b32 %0, [%1];" : "=r"(Af[i][0]) : "r"(ph));
                asm volatile("ld.shared.b32 %0, [%1];" : "=r"(Af[i][1]) : "r"(ph + 8 * PITCH));
                asm volatile("ld.shared.b32 %0, [%1];" : "=r"(Af[i][2]) : "r"(ph + 16));
                asm volatile("ld.shared.b32 %0, [%1];" : "=r"(Af[i][3]) : "r"(ph + 8 * PITCH + 16));
            }
            #pragma unroll
            for (int j = 0; j < 4; j++) {
                uint32_t ph = fB + j * 8 * PITCH + kb;
                asm volatile("ld.shared.b32 %0, [%1];" : "=r"(Bf[j][0]) : "r"(ph));
                asm volatile("ld.shared.b32 %0, [%1];" : "=r"(Bf[j][1]) : "r"(ph + 16));
            }
            #pragma unroll
            for (int i = 0; i < 4; i++)
                #pragma unroll
                for (int j = 0; j < 4; j++)
                    mma16816f(acc[i][j], Af[i], Bf[j]);
        }
        __syncthreads();

        int cn = c + NSTAGE;
        if (cn < CHUNKS) {
            const char* pa = sA + cn * 128;
            const char* pb = sB + cn * 128;
            cpa16(da + so, pa);      cpa16(da + so + 16, pa + 16);
            cpa16(da + so + 32, pa + 32); cpa16(da + so + 48, pa + 48);
            cpa16(db + so, pb);      cpa16(db + so + 16, pb + 16);
            cpa16(db + so + 32, pb + 32); cpa16(db + so + 48, pb + 48);
        }
        CP_COMMIT();
    }

    // epilogue
    #pragma unroll
    for (int i = 0; i < 4; i++) {
        int r0 = mtile * 128 + warp_m * 64 + i * 16 + g;
        #pragma unroll
        for (int j = 0; j < 4; j++) {
            int col = ncol0 + warp_n * 32 + j * 8 + 2 * tig;
            *(float2*)&C[(size_t)r0 * ldc + col]       = make_float2(acc[i][j][0], acc[i][j][1]);
            *(float2*)&C[(size_t)(r0 + 8) * ldc + col] = make_float2(acc[i][j][2], acc[i][j][3]);
        }
    }
}

// ---------------- 3) fused: head-LN(q,k1) + 2x attn + 2x conv1d + LNs + GELUs
__global__ void __launch_bounds__(256, 4)
fused_attn(const float* __restrict__ qv, const float* __restrict__ k1,
           const float* __restrict__ k2n,
           const float* __restrict__ lw, const float* __restrict__ lb,
           const float* __restrict__ l2w, const float* __restrict__ l2b,
           const float* __restrict__ w1, const float* __restrict__ w2,
           float* __restrict__ out) {
    __shared__ float sQ[DIM], sK1[DIM], sK2[DIM], sV[DIM], sO1[DIM];
    __shared__ float cw1[192], cw2[192];
    __shared__ float rs[8], rss[8];
    float* sO2 = sK1;

    int b = blockIdx.x, t = threadIdx.x;
    int wid = t >> 5, lane = t & 31;

    // per-head LN of q (from qv) and k1, each warp = one head
    {
        float x[8], s = 0.f, ss = 0.f;
        #pragma unroll
        for (int j = 0; j < 8; j++) {
            x[j] = qv[(size_t)b * 2 * DIM + wid * HD + lane + 32 * j];
            s += x[j]; ss += x[j] * x[j];
        }
        s = warp_sum(s); ss = warp_sum(ss);
        float mu = s * (1.0f / HD), inv = rsqrtf(ss * (1.0f / HD) - mu * mu + EPS);
        #pragma unroll
        for (int j = 0; j < 8; j++) {
            int i = lane + 32 * j;
            sQ[wid * HD + i] = (x[j] - mu) * inv * lw[i] + lb[i];
        }
    }
    {
        float x[8], s = 0.f, ss = 0.f;
        #pragma unroll
        for (int j = 0; j < 8; j++) {
            x[j] = k1[(size_t)b * DIM + wid * HD + lane + 32 * j];
            s += x[j]; ss += x[j] * x[j];
        }
        s = warp_sum(s); ss = warp_sum(ss);
        float mu = s * (1.0f / HD), inv = rsqrtf(ss * (1.0f / HD) - mu * mu + EPS);
        #pragma unroll
        for (int j = 0; j < 8; j++) {
            int i = lane + 32 * j;
            sK1[wid * HD + i] = (x[j] - mu) * inv * lw[i] + lb[i];
        }
    }
    for (int i = t; i < DIM; i += 256) {
        sK2[i] = k2n[(size_t)b * DIM + i];
        sV[i]  = qv[(size_t)b * 2 * DIM + DIM + i];
    }
    if (t < 192) { cw1[t] = w1[t]; cw2[t] = w2[t]; }
    __syncthreads();

    // ---- attention 1 (sQ vs sK1, value sV) -> sO1 ----
    {
        float a[8];
        #pragma unroll
        for (int s = 0; s < 8; s++) {
            float p = 0.f;
            #pragma unroll
            for (int j = 0; j < 8; j++)
                p = fmaf(sQ[wid * HD + lane + 32 * j], sK1[s * HD + lane + 32 * j], p);
            a[s] = warp_sum(p) * (1.0f / 16.0f);
        }
        float m = a[0];
        #pragma unroll
        for (int s = 1; s < 8; s++) m = fmaxf(m, a[s]);
        float sum = 0.f;
        #pragma unroll
        for (int s = 0; s < 8; s++) { a[s] = expf(a[s] - m); sum += a[s]; }
        float inv = 1.0f / sum;
        #pragma unroll
        for (int j = 0; j < 8; j++) {
            int cc = lane + 32 * j;
            float acc = 0.f;
            #pragma unroll
            for (int s = 0; s < 8; s++) acc = fmaf(a[s], sV[s * HD + cc], acc);
            sO1[wid * HD + cc] = acc * inv;
        }
    }
    __syncthreads();

    // ---- attention 2 (sQ vs sK2) -> sO2 (aliases sK1) ----
    {
        float a[8];
        #pragma unroll
        for (int s = 0; s < 8; s++) {
            float p = 0.f;
            #pragma unroll
            for (int j = 0; j < 8; j++)
                p = fmaf(sQ[wid * HD + lane + 32 * j], sK2[s * HD + lane + 32 * j], p);
            a[s] = warp_sum(p) * (1.0f / 16.0f);
        }
        float m = a[0];
        #pragma unroll
        for (int s = 1; s < 8; s++) m = fmaxf(m, a[s]);
        float sum = 0.f;
        #pragma unroll
        for (int s = 0; s < 8; s++) { a[s] = expf(a[s] - m); sum += a[s]; }
        float inv = 1.0f / sum;
        #pragma unroll
        for (int j = 0; j < 8; j++) {
            int cc = lane + 32 * j;
            float acc = 0.f;
            #pragma unroll
            for (int s = 0; s < 8; s++) acc = fmaf(a[s], sV[s * HD + cc], acc);
            sO2[wid * HD + cc] = acc * inv;
        }
    }
    __syncthreads();

    // ---- conv1d (C=8, K=3, pad 1) + LNs + sum + LN + gelu + LN2 + gelu ----
    float c1[8], c2[8], g[8];
    #pragma unroll
    for (int j = 0; j < 8; j++) {
        int l = lane + 32 * j;
        float a1 = 0.f, a2 = 0.f;
        #pragma unroll
        for (int i = 0; i < 8; i++) {
            float xm = (l > 0)   ? sO1[i * HD + l - 1] : 0.f;
            float x0 =             sO1[i * HD + l];
            float xp = (l < 255) ? sO1[i * HD + l + 1] : 0.f;
            a1 = fmaf(cw1[wid * 24 + i * 3 + 0], xm, a1);
            a1 = fmaf(cw1[wid * 24 + i * 3 + 1], x0, a1);
            a1 = fmaf(cw1[wid * 24 + i * 3 + 2], xp, a1);
            float ym = (l > 0)   ? sO2[i * HD + l - 1] : 0.f;
            float y0 =             sO2[i * HD + l];
            float yp = (l < 255) ? sO2[i * HD + l + 1] : 0.f;
            a2 = fmaf(cw2[wid * 24 + i * 3 + 0], ym, a2);
            a2 = fmaf(cw2[wid * 24 + i * 3 + 1], y0, a2);
            a2 = fmaf(cw2[wid * 24 + i * 3 + 2], yp, a2);
        }
        c1[j] = a1; c2[j] = a2;
    }

    {
        float s = 0.f, ss = 0.f;
        #pragma unroll
        for (int j = 0; j < 8; j++) { s += c1[j]; ss += c1[j] * c1[j]; }
        s = warp_sum(s); ss = warp_sum(ss);
        float mu = s * (1.0f / HD), inv = rsqrtf(ss * (1.0f / HD) - mu * mu + EPS);
        #pragma unroll
        for (int j = 0; j < 8; j++) { int i = lane + 32 * j; c1[j] = (c1[j] - mu) * inv * lw[i] + lb[i]; }
    }
    {
        float s = 0.f, ss = 0.f;
        #pragma unroll
        for (int j = 0; j < 8; j++) { s += c2[j]; ss += c2[j] * c2[j]; }
        s = warp_sum(s); ss = warp_sum(ss);
        float mu = s * (1.0f / HD), inv = rsqrtf(ss * (1.0f / HD) - mu * mu + EPS);
        #pragma unroll
        for (int j = 0; j < 8; j++) { int i = lane + 32 * j; c2[j] = (c2[j] - mu) * inv * lw[i] + lb[i]; }
    }
    {
        float x[8], s = 0.f, ss = 0.f;
        #pragma unroll
        for (int j = 0; j < 8; j++) {
            x[j] = c1[j] + c2[j] + sV[wid * HD + lane + 32 * j];
            s += x[j]; ss += x[j] * x[j];
        }
        s = warp_sum(s); ss = warp_sum(ss);
        float mu = s * (1.0f / HD), inv = rsqrtf(ss * (1.0f / HD) - mu * mu + EPS);
        #pragma unroll
        for (int j = 0; j < 8; j++) {
            int i = lane + 32 * j;
            g[j] = gelu_tanh((x[j] - mu) * inv * lw[i] + lb[i]);
        }
    }
    {
        float s = 0.f, ss = 0.f;
        #pragma unroll
        for (int j = 0; j < 8; j++) { s += g[j]; ss += g[j] * g[j]; }
        s = warp_sum(s); ss = warp_sum(ss);
        if (lane == 0) { rs[wid] = s; rss[wid] = ss; }
        __syncthreads();
        float ts = 0.f, tss = 0.f;
        #pragma unroll
        for (int i = 0; i < 8; i++) { ts += rs[i]; tss += rss[i]; }
        float mu = ts * (1.0f / DIM), inv = rsqrtf(tss * (1.0f / DIM) - mu * mu + EPS);
        #pragma unroll
        for (int j = 0; j < 8; j++) {
            int idx = wid * HD + lane + 32 * j;
            float y = (g[j] - mu) * inv * l2w[idx] + l2b[idx];
            out[(size_t)b * DIM + idx] = gelu_tanh(y);
        }
    }
}

// ---------------- launch ----------------
extern "C" void kernel_launch(void* const* d_in, const int* in_sizes, int n_in,
                              void* d_out, int out_size) {
    const float* f_ad    = (const float*)d_in[0];
    const float* f_age   = (const float*)d_in[1];
    const float* mem     = (const float*)d_in[2];
    const float* age_gap = (const float*)d_in[3];
    const float* qv_W    = (const float*)d_in[4];
    const float* k1_W    = (const float*)d_in[5];
    // d_in[6] = k2_W : dead in the reference — skipped
    const float* ln_w    = (const float*)d_in[7];
    const float* ln_b    = (const float*)d_in[8];
    const float* ln2_w   = (const float*)d_in[9];
    const float* ln2_b   = (const float*)d_in[10];
    const float* agf_rW  = (const float*)d_in[11];
    const float* agf_rb  = (const float*)d_in[12];
    const float* agf_eW  = (const float*)d_in[13];
    const float* agf_eb  = (const float*)d_in[14];
    const float* c1W     = (const float*)d_in[15];
    const float* c2W     = (const float*)d_in[16];
    float* out = (float*)d_out;

    float *qvb, *k1b, *k2n;
    __half *Wqh, *Wkh, *Ahp, *Php;
    cudaGetSymbolAddress((void**)&qvb, g_qv);
    cudaGetSymbolAddress((void**)&k1b, g_k1);
    cudaGetSymbolAddress((void**)&k2n, g_k2n);
    cudaGetSymbolAddress((void**)&Wqh, g_Wqvh);
    cudaGetSymbolAddress((void**)&Wkh, g_Wk1h);
    cudaGetSymbolAddress((void**)&Ahp, g_Ah);
    cudaGetSymbolAddress((void**)&Php, g_Ph);

    cudaFuncSetAttribute(gemm_tc, cudaFuncAttributeMaxDynamicSharedMemorySize, GEMM_SMEM);

    // 1) prep: pool + fp16 converts + AGF (all independent work, one launch)
    prep_kernel<<<NB_PREP, 256>>>(mem, (const float4*)qv_W, (const float4*)k1_W,
                                  (const float4*)f_ad, f_age, age_gap,
                                  agf_rW, agf_rb, agf_eW, agf_eb, ln_w, ln_b,
                                  Php, Wqh, Wkh, Ahp, k2n);
    // 2) tensor-core GEMMs (fp16 1-term)
    gemm_tc<<<dim3(48, 2), 256, GEMM_SMEM>>>(Ahp, Php, Wqh, Wkh, qvb, k1b);
    // 3) fused head-LN + attention + conv + epilogue
    fused_attn<<<B_SZ, 256>>>(qvb, k1b, k2n, ln_w, ln_b, ln2_w, ln2_b, c1W, c2W, out);
}